// round 10
// baseline (speedup 1.0000x reference)
#include <cuda_runtime.h>
#include <cuda_bf16.h>
#include <cstdint>

// Problem constants
#define BB 2
#define SS 2048
#define DD 768
#define HH 12
#define DKK 64
#define NT (BB*SS)
#define OUT_OFF ((size_t)BB*SS*DD)

// Scratch
__device__ float g_V[NT*DD];
__device__ float g_ctx[NT*DD];
// Packed split-bf16 Q/K: [token][head][pair(32)] as uint2 {hi bf16x2, lo bf16x2}
__device__ uint4 g_Qp[NT*HH*16];
__device__ uint4 g_Kp[NT*HH*16];

// ---------------------------------------------------------------------------
// helpers
// ---------------------------------------------------------------------------
__device__ __forceinline__ uint32_t tf32r(float x) {
    uint32_t u; asm("cvt.rna.tf32.f32 %0, %1;" : "=r"(u) : "f"(x)); return u;
}
__device__ __forceinline__ float tf32f(float x) { return __uint_as_float(tf32r(x)); }

__device__ __forceinline__ void mma8(float* c,
    uint32_t a0, uint32_t a1, uint32_t a2, uint32_t a3, uint32_t b0, uint32_t b1)
{
    asm volatile(
        "mma.sync.aligned.m16n8k8.row.col.f32.tf32.tf32.f32 "
        "{%0,%1,%2,%3},{%4,%5,%6,%7},{%8,%9},{%0,%1,%2,%3};"
        : "+f"(c[0]), "+f"(c[1]), "+f"(c[2]), "+f"(c[3])
        : "r"(a0), "r"(a1), "r"(a2), "r"(a3), "r"(b0), "r"(b1));
}

__device__ __forceinline__ void mmabf(float* c,
    uint32_t a0, uint32_t a1, uint32_t a2, uint32_t a3, uint32_t b0, uint32_t b1)
{
    asm volatile(
        "mma.sync.aligned.m16n8k16.row.col.f32.bf16.bf16.f32 "
        "{%0,%1,%2,%3},{%4,%5,%6,%7},{%8,%9},{%0,%1,%2,%3};"
        : "+f"(c[0]), "+f"(c[1]), "+f"(c[2]), "+f"(c[3])
        : "r"(a0), "r"(a1), "r"(a2), "r"(a3), "r"(b0), "r"(b1));
}

// split-bf16 pack of (even, odd) element pair: .x = hi word, .y = lo word
__device__ __forceinline__ uint2 splitpack(float e, float o) {
    __nv_bfloat16 he = __float2bfloat16_rn(e), ho = __float2bfloat16_rn(o);
    float re = e - __bfloat162float(he);
    float ro = o - __bfloat162float(ho);
    __nv_bfloat16 le = __float2bfloat16_rn(re), lo = __float2bfloat16_rn(ro);
    uint2 r;
    r.x = (uint32_t)__bfloat16_as_ushort(he) | ((uint32_t)__bfloat16_as_ushort(ho) << 16);
    r.y = (uint32_t)__bfloat16_as_ushort(le) | ((uint32_t)__bfloat16_as_ushort(lo) << 16);
    return r;
}

// cp.async 16B
__device__ __forceinline__ void cpa16(void* smem_dst, const void* gsrc) {
    uint32_t d = (uint32_t)__cvta_generic_to_shared(smem_dst);
    asm volatile("cp.async.cg.shared.global [%0], [%1], 16;" :: "r"(d), "l"(gsrc));
}
#define CPA_COMMIT asm volatile("cp.async.commit_group;")
#define CPA_WAIT(n) asm volatile("cp.async.wait_group %0;" :: "n"(n))

// ---------------------------------------------------------------------------
// tf32 GEMM (V projection / output GEMM)
// ---------------------------------------------------------------------------
__global__ __launch_bounds__(256)
void gemm_tc(const float* __restrict__ X, const float* __restrict__ W,
             float* __restrict__ C, const float* __restrict__ bias,
             int M, int N, int K)
{
    __shared__ float As[16][132];
    __shared__ float Bs[16][132];

    const int tid  = threadIdx.x;
    const int lane = tid & 31, warp = tid >> 5;
    const int g = lane >> 2, l4 = lane & 3;
    const int wm = warp >> 2, wn = warp & 3;
    const int m0 = blockIdx.y * 128, n0 = blockIdx.x * 128;

    float acc[4][4][4];
#pragma unroll
    for (int i = 0; i < 4; i++)
#pragma unroll
        for (int j = 0; j < 4; j++)
#pragma unroll
            for (int r = 0; r < 4; r++) acc[i][j][r] = 0.f;

    for (int k0 = 0; k0 < K; k0 += 16) {
#pragma unroll
        for (int i = 0; i < 2; i++) {
            int ii = tid + i * 256;
            int row = ii >> 2, kg = (ii & 3) * 4;
            float4 av = *(const float4*)&X[(size_t)(m0 + row) * K + k0 + kg];
            float4 bv = *(const float4*)&W[(size_t)(n0 + row) * K + k0 + kg];
            As[kg+0][row] = tf32f(av.x); As[kg+1][row] = tf32f(av.y);
            As[kg+2][row] = tf32f(av.z); As[kg+3][row] = tf32f(av.w);
            Bs[kg+0][row] = tf32f(bv.x); Bs[kg+1][row] = tf32f(bv.y);
            Bs[kg+2][row] = tf32f(bv.z); Bs[kg+3][row] = tf32f(bv.w);
        }
        __syncthreads();

#pragma unroll
        for (int ks = 0; ks < 2; ks++) {
            uint32_t ah[4][4], bh[4][2];
#pragma unroll
            for (int mt = 0; mt < 4; mt++) {
                int rb = wm * 64 + mt * 16;
                ah[mt][0] = __float_as_uint(As[ks*8 + l4][rb + g]);
                ah[mt][1] = __float_as_uint(As[ks*8 + l4][rb + g + 8]);
                ah[mt][2] = __float_as_uint(As[ks*8 + l4 + 4][rb + g]);
                ah[mt][3] = __float_as_uint(As[ks*8 + l4 + 4][rb + g + 8]);
            }
#pragma unroll
            for (int nt = 0; nt < 4; nt++) {
                int cb = wn * 32 + nt * 8;
                bh[nt][0] = __float_as_uint(Bs[ks*8 + l4][cb + g]);
                bh[nt][1] = __float_as_uint(Bs[ks*8 + l4 + 4][cb + g]);
            }
#pragma unroll
            for (int mt = 0; mt < 4; mt++)
#pragma unroll
                for (int nt = 0; nt < 4; nt++)
                    mma8(acc[mt][nt], ah[mt][0], ah[mt][1], ah[mt][2], ah[mt][3],
                         bh[nt][0], bh[nt][1]);
        }
        __syncthreads();
    }

#pragma unroll
    for (int mt = 0; mt < 4; mt++) {
        int r0 = m0 + wm * 64 + mt * 16 + g;
#pragma unroll
        for (int nt = 0; nt < 4; nt++) {
            int cc = n0 + wn * 32 + nt * 8 + 2 * l4;
            float bx = 0.f, by = 0.f;
            if (bias) { bx = bias[cc]; by = bias[cc + 1]; }
            *(float2*)&C[(size_t)r0 * N + cc] =
                make_float2(acc[mt][nt][0] + bx, acc[mt][nt][1] + by);
            *(float2*)&C[(size_t)(r0 + 8) * N + cc] =
                make_float2(acc[mt][nt][2] + bx, acc[mt][nt][3] + by);
        }
    }
}

// ---------------------------------------------------------------------------
// split-bf16 GEMM for Q/K projections: writes PACKED hi/lo output only.
// ---------------------------------------------------------------------------
__global__ __launch_bounds__(256)
void gemm_bf_pack(const float* __restrict__ X, const float* __restrict__ W,
                  uint2* __restrict__ OutPack, int M, int N, int K)
{
    __shared__ uint2 As[128*8];
    __shared__ uint2 Bs[128*8];

    const int tid  = threadIdx.x;
    const int lane = tid & 31, warp = tid >> 5;
    const int g = lane >> 2, l4 = lane & 3;
    const int wm = warp >> 2, wn = warp & 3;
    const int m0 = blockIdx.y * 128, n0 = blockIdx.x * 128;

    float acc[4][4][4];
#pragma unroll
    for (int i = 0; i < 4; i++)
#pragma unroll
        for (int j = 0; j < 4; j++)
#pragma unroll
            for (int r = 0; r < 4; r++) acc[i][j][r] = 0.f;

    for (int k0 = 0; k0 < K; k0 += 16) {
#pragma unroll
        for (int i = 0; i < 2; i++) {
            int ii = tid + i * 256;
            int row = ii >> 2, kg = (ii & 3) * 4;
            float4 av = *(const float4*)&X[(size_t)(m0 + row) * K + k0 + kg];
            float4 bv = *(const float4*)&W[(size_t)(n0 + row) * K + k0 + kg];
            int p0 = kg >> 1;
            int sw = ((row >> 1) & 1) << 2;
            uint2 wa0 = splitpack(av.x, av.y), wa1 = splitpack(av.z, av.w);
            uint2 wb0 = splitpack(bv.x, bv.y), wb1 = splitpack(bv.z, bv.w);
            *(uint4*)&As[row*8 + (p0 ^ sw)] = make_uint4(wa0.x, wa0.y, wa1.x, wa1.y);
            *(uint4*)&Bs[row*8 + (p0 ^ sw)] = make_uint4(wb0.x, wb0.y, wb1.x, wb1.y);
        }
        __syncthreads();

        uint2 bf[4][2];
#pragma unroll
        for (int nt = 0; nt < 4; nt++) {
            int cb = wn * 32 + nt * 8 + g;
            int sb = ((cb >> 1) & 1) << 2;
            bf[nt][0] = Bs[cb*8 + (l4 ^ sb)];
            bf[nt][1] = Bs[cb*8 + ((l4 + 4) ^ sb)];
        }
#pragma unroll
        for (int mt = 0; mt < 4; mt++) {
            int r = wm * 64 + mt * 16 + g;
            int sa = ((r >> 1) & 1) << 2;
            uint2 a0 = As[r*8 + (l4 ^ sa)];
            uint2 a1 = As[(r+8)*8 + (l4 ^ sa)];
            uint2 a2 = As[r*8 + ((l4 + 4) ^ sa)];
            uint2 a3 = As[(r+8)*8 + ((l4 + 4) ^ sa)];
#pragma unroll
            for (int nt = 0; nt < 4; nt++) {
                mmabf(acc[mt][nt], a0.x, a1.x, a2.x, a3.x, bf[nt][0].y, bf[nt][1].y);
                mmabf(acc[mt][nt], a0.y, a1.y, a2.y, a3.y, bf[nt][0].x, bf[nt][1].x);
                mmabf(acc[mt][nt], a0.x, a1.x, a2.x, a3.x, bf[nt][0].x, bf[nt][1].x);
            }
        }
        __syncthreads();
    }

#pragma unroll
    for (int mt = 0; mt < 4; mt++) {
        int r0 = m0 + wm * 64 + mt * 16 + g;
#pragma unroll
        for (int nt = 0; nt < 4; nt++) {
            int cc = n0 + wn * 32 + nt * 8 + 2 * l4;
            int h = cc >> 6, pg = (cc >> 1) & 31;
            OutPack[((size_t)r0 * HH + h) * 32 + pg] =
                splitpack(acc[mt][nt][0], acc[mt][nt][1]);
            OutPack[((size_t)(r0 + 8) * HH + h) * 32 + pg] =
                splitpack(acc[mt][nt][2], acc[mt][nt][3]);
        }
    }
}

// ---------------------------------------------------------------------------
// K1: scores, split-bf16, cp.async double-buffered K staging.
// Block=(qt64, b, h), 256 thr, warps 2(m)x4(n), warp tile 32x32.
// ---------------------------------------------------------------------------
__global__ __launch_bounds__(256, 2)
void score_bf(const uint2* __restrict__ Qp, const uint2* __restrict__ Kp,
              const int* __restrict__ mask, const float* __restrict__ pb,
              float* __restrict__ Sout)
{
    extern __shared__ uint4 smraw[];
    uint2* sQ = (uint2*)smraw;             // 64*32  = 16KB
    uint2* sK0 = (uint2*)smraw + 64*32;    // 128*32 = 32KB
    uint2* sK1 = sK0 + 128*32;             // 128*32 = 32KB

    const int tid = threadIdx.x;
    const int lane = tid & 31, w = tid >> 5;
    const int g = lane >> 2, l4 = lane & 3;
    const int wm = w >> 2, wn = w & 3;
    const int qt = blockIdx.x, b = blockIdx.y, h = blockIdx.z;
    const int q0 = qt * 64;

    // issue K chunk 0 via cp.async
    {
        const uint4* ksrc = (const uint4*)(Kp + ((size_t)(b*SS) * HH + h) * 32);
#pragma unroll
        for (int i = 0; i < 8; i++) {
            int idx = tid + i * 256;
            int row = idx >> 4, p2 = (idx & 15) * 2;
            int sw = (row & 3) << 2;
            cpa16(&sK0[row*32 + (p2 ^ sw)], &ksrc[(size_t)row * (HH*16) + (p2 >> 1)]);
        }
        CPA_COMMIT;
    }

    // stage Q (plain copy, swizzled) — overlaps with K0 flight
    {
        const uint4* qsrc = (const uint4*)(Qp + ((size_t)(b*SS + q0) * HH + h) * 32);
#pragma unroll
        for (int i = 0; i < 4; i++) {
            int idx = tid + i * 256;
            int row = idx >> 4, p2 = (idx & 15) * 2;
            uint4 v = qsrc[(size_t)row * (HH*16) + (p2 >> 1)];
            int sw = (row & 3) << 2;
            *(uint4*)&sQ[row*32 + (p2 ^ sw)] = v;
        }
    }

    float acc[2][4][4];
#pragma unroll
    for (int mt = 0; mt < 2; mt++)
#pragma unroll
        for (int nt = 0; nt < 4; nt++)
#pragma unroll
            for (int r = 0; r < 4; r++) acc[mt][nt][r] = 0.f;

    for (int kt = 0; kt < SS / 128; kt++) {
        // issue next chunk before waiting on current
        if (kt + 1 < SS / 128) {
            uint2* dst = ((kt + 1) & 1) ? sK1 : sK0;
            const uint4* ksrc = (const uint4*)(Kp + ((size_t)(b*SS + (kt+1)*128) * HH + h) * 32);
#pragma unroll
            for (int i = 0; i < 8; i++) {
                int idx = tid + i * 256;
                int row = idx >> 4, p2 = (idx & 15) * 2;
                int sw = (row & 3) << 2;
                cpa16(&dst[row*32 + (p2 ^ sw)], &ksrc[(size_t)row * (HH*16) + (p2 >> 1)]);
            }
            CPA_COMMIT;
            CPA_WAIT(1);
        } else {
            CPA_WAIT(0);
        }
        __syncthreads();

        const uint2* sK = (kt & 1) ? sK1 : sK0;

#pragma unroll
        for (int s = 0; s < 4; s++) {
            uint2 qa[2][4];
#pragma unroll
            for (int mt = 0; mt < 2; mt++) {
                int r = wm*32 + mt*16 + g;
                int sa = (r & 3) << 2;
                qa[mt][0] = sQ[r*32 + ((8*s + l4) ^ sa)];
                qa[mt][1] = sQ[(r+8)*32 + ((8*s + l4) ^ sa)];
                qa[mt][2] = sQ[r*32 + ((8*s + l4 + 4) ^ sa)];
                qa[mt][3] = sQ[(r+8)*32 + ((8*s + l4 + 4) ^ sa)];
            }
#pragma unroll
            for (int nt = 0; nt < 4; nt++) {
                int key = wn*32 + nt*8 + g;
                int sb = (key & 3) << 2;
                uint2 b0 = sK[key*32 + ((8*s + l4) ^ sb)];
                uint2 b1 = sK[key*32 + ((8*s + l4 + 4) ^ sb)];
#pragma unroll
                for (int mt = 0; mt < 2; mt++) {
                    mmabf(acc[mt][nt], qa[mt][0].x, qa[mt][1].x, qa[mt][2].x, qa[mt][3].x,
                          b0.y, b1.y);
                    mmabf(acc[mt][nt], qa[mt][0].y, qa[mt][1].y, qa[mt][2].y, qa[mt][3].y,
                          b0.x, b1.x);
                    mmabf(acc[mt][nt], qa[mt][0].x, qa[mt][1].x, qa[mt][2].x, qa[mt][3].x,
                          b0.x, b1.x);
                }
            }
        }

        // epilogue: bias+mask, raw score write (cp.async for kt+1 in flight)
#pragma unroll
        for (int mt = 0; mt < 2; mt++) {
            int r0 = q0 + wm*32 + mt*16 + g;
            int r1 = r0 + 8;
#pragma unroll
            for (int nt = 0; nt < 4; nt++) {
                int col = kt*128 + wn*32 + nt*8 + 2*l4;
                float* a = acc[mt][nt];
                float2 pb0 = *(const float2*)&pb[((size_t)h*SS + r0) * SS + col];
                float2 pb1 = *(const float2*)&pb[((size_t)h*SS + r1) * SS + col];
                int2 mk0 = *(const int2*)&mask[((size_t)b*SS + r0) * SS + col];
                int2 mk1 = *(const int2*)&mask[((size_t)b*SS + r1) * SS + col];
                float2 s0, s1;
                s0.x = a[0] * 0.125f + pb0.x; if (mk0.x == 0) s0.x = -1e9f;
                s0.y = a[1] * 0.125f + pb0.y; if (mk0.y == 0) s0.y = -1e9f;
                s1.x = a[2] * 0.125f + pb1.x; if (mk1.x == 0) s1.x = -1e9f;
                s1.y = a[3] * 0.125f + pb1.y; if (mk1.y == 0) s1.y = -1e9f;
                *(float2*)&Sout[((size_t)(b*HH + h)*SS + r0) * SS + col] = s0;
                *(float2*)&Sout[((size_t)(b*HH + h)*SS + r1) * SS + col] = s1;
                a[0] = 0.f; a[1] = 0.f; a[2] = 0.f; a[3] = 0.f;
            }
        }
        __syncthreads();   // all reads of current buffer done before it is re-filled
    }
}

// ---------------------------------------------------------------------------
// K2: row softmax in place. One 128-thread block per (b,h,q) row.
// ---------------------------------------------------------------------------
__global__ __launch_bounds__(128)
void softmax_kernel(float* __restrict__ S)
{
    __shared__ float red[8];
    const size_t base = (size_t)blockIdx.x * SS;
    const int tid = threadIdx.x;
    const int warp = tid >> 5, lane = tid & 31;

    float4 v[4];
#pragma unroll
    for (int i = 0; i < 4; i++)
        v[i] = *(const float4*)&S[base + i*512 + tid*4];

    float mx = -1e30f;
#pragma unroll
    for (int i = 0; i < 4; i++)
        mx = fmaxf(mx, fmaxf(fmaxf(v[i].x, v[i].y), fmaxf(v[i].z, v[i].w)));
#pragma unroll
    for (int o = 16; o; o >>= 1) mx = fmaxf(mx, __shfl_xor_sync(0xffffffffu, mx, o));
    if (lane == 0) red[warp] = mx;
    __syncthreads();
    mx = fmaxf(fmaxf(red[0], red[1]), fmaxf(red[2], red[3]));

    float sum = 0.f;
#pragma unroll
    for (int i = 0; i < 4; i++) {
        v[i].x = __expf(v[i].x - mx); v[i].y = __expf(v[i].y - mx);
        v[i].z = __expf(v[i].z - mx); v[i].w = __expf(v[i].w - mx);
        sum += (v[i].x + v[i].y) + (v[i].z + v[i].w);
    }
#pragma unroll
    for (int o = 16; o; o >>= 1) sum += __shfl_xor_sync(0xffffffffu, sum, o);
    if (lane == 0) red[4 + warp] = sum;
    __syncthreads();
    sum = (red[4] + red[5]) + (red[6] + red[7]);

    float rinv = 1.f / sum;
#pragma unroll
    for (int i = 0; i < 4; i++) {
        v[i].x *= rinv; v[i].y *= rinv; v[i].z *= rinv; v[i].w *= rinv;
        *(float4*)&S[base + i*512 + tid*4] = v[i];
    }
}

// ---------------------------------------------------------------------------
// K3: ctx = P @ V (tf32). Block=(qt128, b, h), 256 thr, warps 4(m)x2(n).
// ---------------------------------------------------------------------------
#define PSTR 132
#define VSTR 68

__global__ __launch_bounds__(256)
void pv_kernel(const float* __restrict__ P, const float* __restrict__ V,
               float* __restrict__ ctx)
{
    extern __shared__ float sm[];
    float* Ps = sm;                 // 128 * PSTR
    float* Vs = sm + 128 * PSTR;    // 128 * VSTR

    const int tid = threadIdx.x;
    const int lane = tid & 31, w = tid >> 5;
    const int g = lane >> 2, l4 = lane & 3;
    const int wm = w >> 1, wn = w & 1;
    const int qt = blockIdx.x, b = blockIdx.y, h = blockIdx.z;
    const int q0 = qt * 128;

    float acc[2][4][4];
#pragma unroll
    for (int mt = 0; mt < 2; mt++)
#pragma unroll
        for (int nt = 0; nt < 4; nt++)
#pragma unroll
            for (int r = 0; r < 4; r++) acc[mt][nt][r] = 0.f;

    for (int kt = 0; kt < SS / 128; kt++) {
        __syncthreads();
#pragma unroll
        for (int i = 0; i < 16; i++) {
            int idx = tid + i * 256;
            int row = idx >> 5, c4 = (idx & 31) * 4;
            float4 v = *(const float4*)&P[((size_t)(b*HH + h)*SS + q0 + row) * SS + kt*128 + c4];
            v.x = tf32f(v.x); v.y = tf32f(v.y); v.z = tf32f(v.z); v.w = tf32f(v.w);
            *(float4*)&Ps[row * PSTR + c4] = v;
        }
#pragma unroll
        for (int i = 0; i < 8; i++) {
            int idx = tid + i * 256;
            int row = idx >> 4, c4 = (idx & 15) * 4;
            float4 v = *(const float4*)&V[(size_t)(b*SS + kt*128 + row) * DD + h*DKK + c4];
            v.x = tf32f(v.x); v.y = tf32f(v.y); v.z = tf32f(v.z); v.w = tf32f(v.w);
            *(float4*)&Vs[row * VSTR + c4] = v;
        }
        __syncthreads();

#pragma unroll
        for (int ks = 0; ks < 16; ks++) {
            uint32_t a[2][4];
#pragma unroll
            for (int mt = 0; mt < 2; mt++) {
                int r = wm*32 + mt*16 + g;
                a[mt][0] = __float_as_uint(Ps[r * PSTR + ks*8 + l4]);
                a[mt][1] = __float_as_uint(Ps[(r+8) * PSTR + ks*8 + l4]);
                a[mt][2] = __float_as_uint(Ps[r * PSTR + ks*8 + l4 + 4]);
                a[mt][3] = __float_as_uint(Ps[(r+8) * PSTR + ks*8 + l4 + 4]);
            }
#pragma unroll
            for (int nt = 0; nt < 4; nt++) {
                int col = wn*32 + nt*8 + g;
                uint32_t b0 = __float_as_uint(Vs[(ks*8 + l4) * VSTR + col]);
                uint32_t b1 = __float_as_uint(Vs[(ks*8 + l4 + 4) * VSTR + col]);
#pragma unroll
                for (int mt = 0; mt < 2; mt++)
                    mma8(acc[mt][nt], a[mt][0], a[mt][1], a[mt][2], a[mt][3], b0, b1);
            }
        }
    }

#pragma unroll
    for (int mt = 0; mt < 2; mt++) {
        int r0 = q0 + wm*32 + mt*16 + g;
#pragma unroll
        for (int nt = 0; nt < 4; nt++) {
            int cc = h*DKK + wn*32 + nt*8 + 2*l4;
            *(float2*)&ctx[(size_t)(b*SS + r0) * DD + cc] =
                make_float2(acc[mt][nt][0], acc[mt][nt][1]);
            *(float2*)&ctx[(size_t)(b*SS + r0 + 8) * DD + cc] =
                make_float2(acc[mt][nt][2], acc[mt][nt][3]);
        }
    }
}

// ---------------------------------------------------------------------------
// Launch
// ---------------------------------------------------------------------------
extern "C" void kernel_launch(void* const* d_in, const int* in_sizes, int n_in,
                              void* d_out, int out_size)
{
    const float* query = (const float*)d_in[0];
    const float* key   = (const float*)d_in[1];
    const float* value = (const float*)d_in[2];
    const int*   mask  = (const int*)  d_in[3];
    const float* pb    = (const float*)d_in[4];
    const float* Wq    = (const float*)d_in[5];
    const float* Wk    = (const float*)d_in[6];
    const float* Wv    = (const float*)d_in[7];
    const float* Wo    = (const float*)d_in[8];
    const float* bo    = (const float*)d_in[9];
    float* out = (float*)d_out;
    float* attn = out + OUT_OFF;

    float *pV, *pC;
    uint4 *pQp, *pKp;
    cudaGetSymbolAddress((void**)&pV,  g_V);
    cudaGetSymbolAddress((void**)&pC,  g_ctx);
    cudaGetSymbolAddress((void**)&pQp, g_Qp);
    cudaGetSymbolAddress((void**)&pKp, g_Kp);

    const int SC_SMEM = (64*32 + 2*128*32) * sizeof(uint2);          // 81920
    const int PV_SMEM = (128*PSTR + 128*VSTR) * sizeof(float);       // 102400
    cudaFuncSetAttribute(score_bf,
                         cudaFuncAttributeMaxDynamicSharedMemorySize, SC_SMEM);
    cudaFuncSetAttribute(pv_kernel,
                         cudaFuncAttributeMaxDynamicSharedMemorySize, PV_SMEM);

    dim3 gg(DD / 128, NT / 128);   // (6, 32)
    gemm_bf_pack<<<gg, 256>>>(query, Wq, (uint2*)pQp, NT, DD, DD);
    gemm_bf_pack<<<gg, 256>>>(key,   Wk, (uint2*)pKp, NT, DD, DD);
    gemm_tc<<<gg, 256>>>(value, Wv, pV, nullptr, NT, DD, DD);

    dim3 gs(SS / 64, BB, HH);      // (32, 2, 12) — h slowest for L2 reuse
    score_bf<<<gs, 256, SC_SMEM>>>((const uint2*)pQp, (const uint2*)pKp,
                                   mask, pb, attn);

    softmax_kernel<<<BB * HH * SS, 128>>>(attn);

    dim3 gp(SS / 128, BB, HH);     // (16, 2, 12)
    pv_kernel<<<gp, 256, PV_SMEM>>>(attn, pV, pC);

    gemm_tc<<<gg, 256>>>(pC, Wo, out, bo, NT, DD, DD);
}

// round 12
// speedup vs baseline: 1.2704x; 1.2704x over previous
#include <cuda_runtime.h>
#include <cuda_bf16.h>
#include <cstdint>

// Problem constants
#define BB 2
#define SS 2048
#define DD 768
#define HH 12
#define DKK 64
#define NT (BB*SS)
#define OUT_OFF ((size_t)BB*SS*DD)

// Scratch
__device__ float g_V[NT*DD];
__device__ float g_ctx[NT*DD];
// Packed split-bf16 Q/K: [token][head][pair(32)] as uint2 {hi bf16x2, lo bf16x2}
__device__ uint4 g_Qp[NT*HH*16];
__device__ uint4 g_Kp[NT*HH*16];

// ---------------------------------------------------------------------------
// helpers
// ---------------------------------------------------------------------------
__device__ __forceinline__ uint32_t tf32r(float x) {
    uint32_t u; asm("cvt.rna.tf32.f32 %0, %1;" : "=r"(u) : "f"(x)); return u;
}
__device__ __forceinline__ float tf32f(float x) { return __uint_as_float(tf32r(x)); }

__device__ __forceinline__ void mma8(float* c,
    uint32_t a0, uint32_t a1, uint32_t a2, uint32_t a3, uint32_t b0, uint32_t b1)
{
    asm volatile(
        "mma.sync.aligned.m16n8k8.row.col.f32.tf32.tf32.f32 "
        "{%0,%1,%2,%3},{%4,%5,%6,%7},{%8,%9},{%0,%1,%2,%3};"
        : "+f"(c[0]), "+f"(c[1]), "+f"(c[2]), "+f"(c[3])
        : "r"(a0), "r"(a1), "r"(a2), "r"(a3), "r"(b0), "r"(b1));
}

__device__ __forceinline__ void mmabf(float* c,
    uint32_t a0, uint32_t a1, uint32_t a2, uint32_t a3, uint32_t b0, uint32_t b1)
{
    asm volatile(
        "mma.sync.aligned.m16n8k16.row.col.f32.bf16.bf16.f32 "
        "{%0,%1,%2,%3},{%4,%5,%6,%7},{%8,%9},{%0,%1,%2,%3};"
        : "+f"(c[0]), "+f"(c[1]), "+f"(c[2]), "+f"(c[3])
        : "r"(a0), "r"(a1), "r"(a2), "r"(a3), "r"(b0), "r"(b1));
}

// split-bf16 pack of (even, odd) element pair: .x = hi word, .y = lo word
__device__ __forceinline__ uint2 splitpack(float e, float o) {
    __nv_bfloat16 he = __float2bfloat16_rn(e), ho = __float2bfloat16_rn(o);
    float re = e - __bfloat162float(he);
    float ro = o - __bfloat162float(ho);
    __nv_bfloat16 le = __float2bfloat16_rn(re), lo = __float2bfloat16_rn(ro);
    uint2 r;
    r.x = (uint32_t)__bfloat16_as_ushort(he) | ((uint32_t)__bfloat16_as_ushort(ho) << 16);
    r.y = (uint32_t)__bfloat16_as_ushort(le) | ((uint32_t)__bfloat16_as_ushort(lo) << 16);
    return r;
}

// ---------------------------------------------------------------------------
// tf32 GEMM (V projection / output GEMM), register-prefetch pipelined
// ---------------------------------------------------------------------------
__global__ __launch_bounds__(256)
void gemm_tc(const float* __restrict__ X, const float* __restrict__ W,
             float* __restrict__ C, const float* __restrict__ bias,
             int M, int N, int K)
{
    __shared__ float As[16][132];
    __shared__ float Bs[16][132];

    const int tid  = threadIdx.x;
    const int lane = tid & 31, warp = tid >> 5;
    const int g = lane >> 2, l4 = lane & 3;
    const int wm = warp >> 2, wn = warp & 3;
    const int m0 = blockIdx.y * 128, n0 = blockIdx.x * 128;

    float acc[4][4][4];
#pragma unroll
    for (int i = 0; i < 4; i++)
#pragma unroll
        for (int j = 0; j < 4; j++)
#pragma unroll
            for (int r = 0; r < 4; r++) acc[i][j][r] = 0.f;

    // prefetch tile 0
    float4 pa[2], pbv[2];
#pragma unroll
    for (int i = 0; i < 2; i++) {
        int ii = tid + i * 256;
        int row = ii >> 2, kg = (ii & 3) * 4;
        pa[i]  = *(const float4*)&X[(size_t)(m0 + row) * K + kg];
        pbv[i] = *(const float4*)&W[(size_t)(n0 + row) * K + kg];
    }

    for (int k0 = 0; k0 < K; k0 += 16) {
        // store current tile
#pragma unroll
        for (int i = 0; i < 2; i++) {
            int ii = tid + i * 256;
            int row = ii >> 2, kg = (ii & 3) * 4;
            As[kg+0][row] = tf32f(pa[i].x);  As[kg+1][row] = tf32f(pa[i].y);
            As[kg+2][row] = tf32f(pa[i].z);  As[kg+3][row] = tf32f(pa[i].w);
            Bs[kg+0][row] = tf32f(pbv[i].x); Bs[kg+1][row] = tf32f(pbv[i].y);
            Bs[kg+2][row] = tf32f(pbv[i].z); Bs[kg+3][row] = tf32f(pbv[i].w);
        }
        __syncthreads();

        // issue next tile's loads (latency hidden under mma)
        if (k0 + 16 < K) {
#pragma unroll
            for (int i = 0; i < 2; i++) {
                int ii = tid + i * 256;
                int row = ii >> 2, kg = (ii & 3) * 4;
                pa[i]  = *(const float4*)&X[(size_t)(m0 + row) * K + k0 + 16 + kg];
                pbv[i] = *(const float4*)&W[(size_t)(n0 + row) * K + k0 + 16 + kg];
            }
        }

#pragma unroll
        for (int ks = 0; ks < 2; ks++) {
            uint32_t ah[4][4], bh[4][2];
#pragma unroll
            for (int mt = 0; mt < 4; mt++) {
                int rb = wm * 64 + mt * 16;
                ah[mt][0] = __float_as_uint(As[ks*8 + l4][rb + g]);
                ah[mt][1] = __float_as_uint(As[ks*8 + l4][rb + g + 8]);
                ah[mt][2] = __float_as_uint(As[ks*8 + l4 + 4][rb + g]);
                ah[mt][3] = __float_as_uint(As[ks*8 + l4 + 4][rb + g + 8]);
            }
#pragma unroll
            for (int nt = 0; nt < 4; nt++) {
                int cb = wn * 32 + nt * 8;
                bh[nt][0] = __float_as_uint(Bs[ks*8 + l4][cb + g]);
                bh[nt][1] = __float_as_uint(Bs[ks*8 + l4 + 4][cb + g]);
            }
#pragma unroll
            for (int mt = 0; mt < 4; mt++)
#pragma unroll
                for (int nt = 0; nt < 4; nt++)
                    mma8(acc[mt][nt], ah[mt][0], ah[mt][1], ah[mt][2], ah[mt][3],
                         bh[nt][0], bh[nt][1]);
        }
        __syncthreads();
    }

#pragma unroll
    for (int mt = 0; mt < 4; mt++) {
        int r0 = m0 + wm * 64 + mt * 16 + g;
#pragma unroll
        for (int nt = 0; nt < 4; nt++) {
            int cc = n0 + wn * 32 + nt * 8 + 2 * l4;
            float bx = 0.f, by = 0.f;
            if (bias) { bx = bias[cc]; by = bias[cc + 1]; }
            *(float2*)&C[(size_t)r0 * N + cc] =
                make_float2(acc[mt][nt][0] + bx, acc[mt][nt][1] + by);
            *(float2*)&C[(size_t)(r0 + 8) * N + cc] =
                make_float2(acc[mt][nt][2] + bx, acc[mt][nt][3] + by);
        }
    }
}

// ---------------------------------------------------------------------------
// split-bf16 GEMM for Q/K projections, register-prefetch pipelined.
// Writes PACKED hi/lo output.
// ---------------------------------------------------------------------------
__global__ __launch_bounds__(256)
void gemm_bf_pack(const float* __restrict__ X, const float* __restrict__ W,
                  uint2* __restrict__ OutPack, int M, int N, int K)
{
    __shared__ uint2 As[128*8];
    __shared__ uint2 Bs[128*8];

    const int tid  = threadIdx.x;
    const int lane = tid & 31, warp = tid >> 5;
    const int g = lane >> 2, l4 = lane & 3;
    const int wm = warp >> 2, wn = warp & 3;
    const int m0 = blockIdx.y * 128, n0 = blockIdx.x * 128;

    float acc[4][4][4];
#pragma unroll
    for (int i = 0; i < 4; i++)
#pragma unroll
        for (int j = 0; j < 4; j++)
#pragma unroll
            for (int r = 0; r < 4; r++) acc[i][j][r] = 0.f;

    // prefetch tile 0
    float4 pa[2], pbv[2];
#pragma unroll
    for (int i = 0; i < 2; i++) {
        int ii = tid + i * 256;
        int row = ii >> 2, kg = (ii & 3) * 4;
        pa[i]  = *(const float4*)&X[(size_t)(m0 + row) * K + kg];
        pbv[i] = *(const float4*)&W[(size_t)(n0 + row) * K + kg];
    }

    for (int k0 = 0; k0 < K; k0 += 16) {
#pragma unroll
        for (int i = 0; i < 2; i++) {
            int ii = tid + i * 256;
            int row = ii >> 2, kg = (ii & 3) * 4;
            int p0 = kg >> 1;
            int sw = ((row >> 1) & 1) << 2;
            uint2 wa0 = splitpack(pa[i].x, pa[i].y), wa1 = splitpack(pa[i].z, pa[i].w);
            uint2 wb0 = splitpack(pbv[i].x, pbv[i].y), wb1 = splitpack(pbv[i].z, pbv[i].w);
            *(uint4*)&As[row*8 + (p0 ^ sw)] = make_uint4(wa0.x, wa0.y, wa1.x, wa1.y);
            *(uint4*)&Bs[row*8 + (p0 ^ sw)] = make_uint4(wb0.x, wb0.y, wb1.x, wb1.y);
        }
        __syncthreads();

        if (k0 + 16 < K) {
#pragma unroll
            for (int i = 0; i < 2; i++) {
                int ii = tid + i * 256;
                int row = ii >> 2, kg = (ii & 3) * 4;
                pa[i]  = *(const float4*)&X[(size_t)(m0 + row) * K + k0 + 16 + kg];
                pbv[i] = *(const float4*)&W[(size_t)(n0 + row) * K + k0 + 16 + kg];
            }
        }

        uint2 bf[4][2];
#pragma unroll
        for (int nt = 0; nt < 4; nt++) {
            int cb = wn * 32 + nt * 8 + g;
            int sb = ((cb >> 1) & 1) << 2;
            bf[nt][0] = Bs[cb*8 + (l4 ^ sb)];
            bf[nt][1] = Bs[cb*8 + ((l4 + 4) ^ sb)];
        }
#pragma unroll
        for (int mt = 0; mt < 4; mt++) {
            int r = wm * 64 + mt * 16 + g;
            int sa = ((r >> 1) & 1) << 2;
            uint2 a0 = As[r*8 + (l4 ^ sa)];
            uint2 a1 = As[(r+8)*8 + (l4 ^ sa)];
            uint2 a2 = As[r*8 + ((l4 + 4) ^ sa)];
            uint2 a3 = As[(r+8)*8 + ((l4 + 4) ^ sa)];
#pragma unroll
            for (int nt = 0; nt < 4; nt++) {
                mmabf(acc[mt][nt], a0.x, a1.x, a2.x, a3.x, bf[nt][0].y, bf[nt][1].y);
                mmabf(acc[mt][nt], a0.y, a1.y, a2.y, a3.y, bf[nt][0].x, bf[nt][1].x);
                mmabf(acc[mt][nt], a0.x, a1.x, a2.x, a3.x, bf[nt][0].x, bf[nt][1].x);
            }
        }
        __syncthreads();
    }

#pragma unroll
    for (int mt = 0; mt < 4; mt++) {
        int r0 = m0 + wm * 64 + mt * 16 + g;
#pragma unroll
        for (int nt = 0; nt < 4; nt++) {
            int cc = n0 + wn * 32 + nt * 8 + 2 * l4;
            int h = cc >> 6, pg = (cc >> 1) & 31;
            OutPack[((size_t)r0 * HH + h) * 32 + pg] =
                splitpack(acc[mt][nt][0], acc[mt][nt][1]);
            OutPack[((size_t)(r0 + 8) * HH + h) * 32 + pg] =
                splitpack(acc[mt][nt][2], acc[mt][nt][3]);
        }
    }
}

// ---------------------------------------------------------------------------
// K1: scores, split-bf16. Block=(qt128, b, h), 512 thr, warps 4(m)x4(n),
// warp tile 32x32 (validated shape). Plain LDG staging (L1-friendly).
// ---------------------------------------------------------------------------
__global__ __launch_bounds__(512, 1)
void score_bf(const uint2* __restrict__ Qp, const uint2* __restrict__ Kp,
              const int* __restrict__ mask, const float* __restrict__ pb,
              float* __restrict__ Sout)
{
    extern __shared__ uint4 smraw[];
    uint2* sQ = (uint2*)smraw;            // 128*32 = 32KB
    uint2* sK = (uint2*)smraw + 128*32;   // 128*32 = 32KB

    const int tid = threadIdx.x;
    const int lane = tid & 31, w = tid >> 5;
    const int g = lane >> 2, l4 = lane & 3;
    const int wm = w >> 2, wn = w & 3;     // 4 x 4 warps
    const int qt = blockIdx.x, b = blockIdx.y, h = blockIdx.z;
    const int q0 = qt * 128;

    // stage Q (pure copy, swizzled): 128 rows x 16 uint4
    {
        const uint4* qsrc = (const uint4*)(Qp + ((size_t)(b*SS + q0) * HH + h) * 32);
#pragma unroll
        for (int i = 0; i < 4; i++) {
            int idx = tid + i * 512;          // 2048 uint4
            int row = idx >> 4, p2 = (idx & 15) * 2;
            uint4 v = qsrc[(size_t)row * (HH*16) + (p2 >> 1)];
            int sw = (row & 3) << 2;
            *(uint4*)&sQ[row*32 + (p2 ^ sw)] = v;
        }
    }

    float acc[2][4][4];
#pragma unroll
    for (int mt = 0; mt < 2; mt++)
#pragma unroll
        for (int nt = 0; nt < 4; nt++)
#pragma unroll
            for (int r = 0; r < 4; r++) acc[mt][nt][r] = 0.f;

    for (int kt = 0; kt < SS / 128; kt++) {
        __syncthreads();
        const uint4* ksrc = (const uint4*)(Kp + ((size_t)(b*SS + kt*128) * HH + h) * 32);
#pragma unroll
        for (int i = 0; i < 4; i++) {
            int idx = tid + i * 512;          // 2048 uint4
            int row = idx >> 4, p2 = (idx & 15) * 2;
            uint4 v = ksrc[(size_t)row * (HH*16) + (p2 >> 1)];
            int sw = (row & 3) << 2;
            *(uint4*)&sK[row*32 + (p2 ^ sw)] = v;
        }
        __syncthreads();

#pragma unroll
        for (int s = 0; s < 4; s++) {
            uint2 qa[2][4];
#pragma unroll
            for (int mt = 0; mt < 2; mt++) {
                int r = wm*32 + mt*16 + g;
                int sa = (r & 3) << 2;
                qa[mt][0] = sQ[r*32 + ((8*s + l4) ^ sa)];
                qa[mt][1] = sQ[(r+8)*32 + ((8*s + l4) ^ sa)];
                qa[mt][2] = sQ[r*32 + ((8*s + l4 + 4) ^ sa)];
                qa[mt][3] = sQ[(r+8)*32 + ((8*s + l4 + 4) ^ sa)];
            }
#pragma unroll
            for (int nt = 0; nt < 4; nt++) {
                int key = wn*32 + nt*8 + g;
                int sb = (key & 3) << 2;
                uint2 b0 = sK[key*32 + ((8*s + l4) ^ sb)];
                uint2 b1 = sK[key*32 + ((8*s + l4 + 4) ^ sb)];
#pragma unroll
                for (int mt = 0; mt < 2; mt++) {
                    mmabf(acc[mt][nt], qa[mt][0].x, qa[mt][1].x, qa[mt][2].x, qa[mt][3].x,
                          b0.y, b1.y);
                    mmabf(acc[mt][nt], qa[mt][0].y, qa[mt][1].y, qa[mt][2].y, qa[mt][3].y,
                          b0.x, b1.x);
                    mmabf(acc[mt][nt], qa[mt][0].x, qa[mt][1].x, qa[mt][2].x, qa[mt][3].x,
                          b0.x, b1.x);
                }
            }
        }

        // epilogue for this key chunk
#pragma unroll
        for (int mt = 0; mt < 2; mt++) {
            int r0 = q0 + wm*32 + mt*16 + g;
            int r1 = r0 + 8;
#pragma unroll
            for (int nt = 0; nt < 4; nt++) {
                int col = kt*128 + wn*32 + nt*8 + 2*l4;
                float* a = acc[mt][nt];
                float2 pb0 = *(const float2*)&pb[((size_t)h*SS + r0) * SS + col];
                float2 pb1 = *(const float2*)&pb[((size_t)h*SS + r1) * SS + col];
                int2 mk0 = *(const int2*)&mask[((size_t)b*SS + r0) * SS + col];
                int2 mk1 = *(const int2*)&mask[((size_t)b*SS + r1) * SS + col];
                float2 s0, s1;
                s0.x = a[0] * 0.125f + pb0.x; if (mk0.x == 0) s0.x = -1e9f;
                s0.y = a[1] * 0.125f + pb0.y; if (mk0.y == 0) s0.y = -1e9f;
                s1.x = a[2] * 0.125f + pb1.x; if (mk1.x == 0) s1.x = -1e9f;
                s1.y = a[3] * 0.125f + pb1.y; if (mk1.y == 0) s1.y = -1e9f;
                *(float2*)&Sout[((size_t)(b*HH + h)*SS + r0) * SS + col] = s0;
                *(float2*)&Sout[((size_t)(b*HH + h)*SS + r1) * SS + col] = s1;
                a[0] = 0.f; a[1] = 0.f; a[2] = 0.f; a[3] = 0.f;
            }
        }
    }
}

// ---------------------------------------------------------------------------
// K2: row softmax in place. One 128-thread block per (b,h,q) row.
// ---------------------------------------------------------------------------
__global__ __launch_bounds__(128)
void softmax_kernel(float* __restrict__ S)
{
    __shared__ float red[8];
    const size_t base = (size_t)blockIdx.x * SS;
    const int tid = threadIdx.x;
    const int warp = tid >> 5, lane = tid & 31;

    float4 v[4];
#pragma unroll
    for (int i = 0; i < 4; i++)
        v[i] = *(const float4*)&S[base + i*512 + tid*4];

    float mx = -1e30f;
#pragma unroll
    for (int i = 0; i < 4; i++)
        mx = fmaxf(mx, fmaxf(fmaxf(v[i].x, v[i].y), fmaxf(v[i].z, v[i].w)));
#pragma unroll
    for (int o = 16; o; o >>= 1) mx = fmaxf(mx, __shfl_xor_sync(0xffffffffu, mx, o));
    if (lane == 0) red[warp] = mx;
    __syncthreads();
    mx = fmaxf(fmaxf(red[0], red[1]), fmaxf(red[2], red[3]));

    float sum = 0.f;
#pragma unroll
    for (int i = 0; i < 4; i++) {
        v[i].x = __expf(v[i].x - mx); v[i].y = __expf(v[i].y - mx);
        v[i].z = __expf(v[i].z - mx); v[i].w = __expf(v[i].w - mx);
        sum += (v[i].x + v[i].y) + (v[i].z + v[i].w);
    }
#pragma unroll
    for (int o = 16; o; o >>= 1) sum += __shfl_xor_sync(0xffffffffu, sum, o);
    if (lane == 0) red[4 + warp] = sum;
    __syncthreads();
    sum = (red[4] + red[5]) + (red[6] + red[7]);

    float rinv = 1.f / sum;
#pragma unroll
    for (int i = 0; i < 4; i++) {
        v[i].x *= rinv; v[i].y *= rinv; v[i].z *= rinv; v[i].w *= rinv;
        *(float4*)&S[base + i*512 + tid*4] = v[i];
    }
}

// ---------------------------------------------------------------------------
// K3: ctx = P @ V (tf32). Block=(qt128, b, h), 256 thr, warps 4(m)x2(n).
// ---------------------------------------------------------------------------
#define PSTR 132
#define VSTR 68

__global__ __launch_bounds__(256)
void pv_kernel(const float* __restrict__ P, const float* __restrict__ V,
               float* __restrict__ ctx)
{
    extern __shared__ float sm[];
    float* Ps = sm;                 // 128 * PSTR
    float* Vs = sm + 128 * PSTR;    // 128 * VSTR

    const int tid = threadIdx.x;
    const int lane = tid & 31, w = tid >> 5;
    const int g = lane >> 2, l4 = lane & 3;
    const int wm = w >> 1, wn = w & 1;
    const int qt = blockIdx.x, b = blockIdx.y, h = blockIdx.z;
    const int q0 = qt * 128;

    float acc[2][4][4];
#pragma unroll
    for (int mt = 0; mt < 2; mt++)
#pragma unroll
        for (int nt = 0; nt < 4; nt++)
#pragma unroll
            for (int r = 0; r < 4; r++) acc[mt][nt][r] = 0.f;

    for (int kt = 0; kt < SS / 128; kt++) {
        __syncthreads();
#pragma unroll
        for (int i = 0; i < 16; i++) {
            int idx = tid + i * 256;
            int row = idx >> 5, c4 = (idx & 31) * 4;
            float4 v = *(const float4*)&P[((size_t)(b*HH + h)*SS + q0 + row) * SS + kt*128 + c4];
            v.x = tf32f(v.x); v.y = tf32f(v.y); v.z = tf32f(v.z); v.w = tf32f(v.w);
            *(float4*)&Ps[row * PSTR + c4] = v;
        }
#pragma unroll
        for (int i = 0; i < 8; i++) {
            int idx = tid + i * 256;
            int row = idx >> 4, c4 = (idx & 15) * 4;
            float4 v = *(const float4*)&V[(size_t)(b*SS + kt*128 + row) * DD + h*DKK + c4];
            v.x = tf32f(v.x); v.y = tf32f(v.y); v.z = tf32f(v.z); v.w = tf32f(v.w);
            *(float4*)&Vs[row * VSTR + c4] = v;
        }
        __syncthreads();

#pragma unroll
        for (int ks = 0; ks < 16; ks++) {
            uint32_t a[2][4];
#pragma unroll
            for (int mt = 0; mt < 2; mt++) {
                int r = wm*32 + mt*16 + g;
                a[mt][0] = __float_as_uint(Ps[r * PSTR + ks*8 + l4]);
                a[mt][1] = __float_as_uint(Ps[(r+8) * PSTR + ks*8 + l4]);
                a[mt][2] = __float_as_uint(Ps[r * PSTR + ks*8 + l4 + 4]);
                a[mt][3] = __float_as_uint(Ps[(r+8) * PSTR + ks*8 + l4 + 4]);
            }
#pragma unroll
            for (int nt = 0; nt < 4; nt++) {
                int col = wn*32 + nt*8 + g;
                uint32_t b0 = __float_as_uint(Vs[(ks*8 + l4) * VSTR + col]);
                uint32_t b1 = __float_as_uint(Vs[(ks*8 + l4 + 4) * VSTR + col]);
#pragma unroll
                for (int mt = 0; mt < 2; mt++)
                    mma8(acc[mt][nt], a[mt][0], a[mt][1], a[mt][2], a[mt][3], b0, b1);
            }
        }
    }

#pragma unroll
    for (int mt = 0; mt < 2; mt++) {
        int r0 = q0 + wm*32 + mt*16 + g;
#pragma unroll
        for (int nt = 0; nt < 4; nt++) {
            int cc = h*DKK + wn*32 + nt*8 + 2*l4;
            *(float2*)&ctx[(size_t)(b*SS + r0) * DD + cc] =
                make_float2(acc[mt][nt][0], acc[mt][nt][1]);
            *(float2*)&ctx[(size_t)(b*SS + r0 + 8) * DD + cc] =
                make_float2(acc[mt][nt][2], acc[mt][nt][3]);
        }
    }
}

// ---------------------------------------------------------------------------
// Launch
// ---------------------------------------------------------------------------
extern "C" void kernel_launch(void* const* d_in, const int* in_sizes, int n_in,
                              void* d_out, int out_size)
{
    const float* query = (const float*)d_in[0];
    const float* key   = (const float*)d_in[1];
    const float* value = (const float*)d_in[2];
    const int*   mask  = (const int*)  d_in[3];
    const float* pb    = (const float*)d_in[4];
    const float* Wq    = (const float*)d_in[5];
    const float* Wk    = (const float*)d_in[6];
    const float* Wv    = (const float*)d_in[7];
    const float* Wo    = (const float*)d_in[8];
    const float* bo    = (const float*)d_in[9];
    float* out = (float*)d_out;
    float* attn = out + OUT_OFF;

    float *pV, *pC;
    uint4 *pQp, *pKp;
    cudaGetSymbolAddress((void**)&pV,  g_V);
    cudaGetSymbolAddress((void**)&pC,  g_ctx);
    cudaGetSymbolAddress((void**)&pQp, g_Qp);
    cudaGetSymbolAddress((void**)&pKp, g_Kp);

    const int SC_SMEM = (128*32 + 128*32) * sizeof(uint2);           // 65536
    const int PV_SMEM = (128*PSTR + 128*VSTR) * sizeof(float);       // 102400
    cudaFuncSetAttribute(score_bf,
                         cudaFuncAttributeMaxDynamicSharedMemorySize, SC_SMEM);
    cudaFuncSetAttribute(pv_kernel,
                         cudaFuncAttributeMaxDynamicSharedMemorySize, PV_SMEM);

    dim3 gg(DD / 128, NT / 128);   // (6, 32)
    gemm_bf_pack<<<gg, 256>>>(query, Wq, (uint2*)pQp, NT, DD, DD);
    gemm_bf_pack<<<gg, 256>>>(key,   Wk, (uint2*)pKp, NT, DD, DD);
    gemm_tc<<<gg, 256>>>(value, Wv, pV, nullptr, NT, DD, DD);

    dim3 gs(SS / 128, BB, HH);     // (16, 2, 12) — h slowest for L2 reuse
    score_bf<<<gs, 512, SC_SMEM>>>((const uint2*)pQp, (const uint2*)pKp,
                                   mask, pb, attn);

    softmax_kernel<<<BB * HH * SS, 128>>>(attn);

    dim3 gp(SS / 128, BB, HH);     // (16, 2, 12)
    pv_kernel<<<gp, 256, PV_SMEM>>>(attn, pV, pC);

    gemm_tc<<<gg, 256>>>(pC, Wo, out, bo, NT, DD, DD);
}

// round 13
// speedup vs baseline: 1.4510x; 1.1422x over previous
#include <cuda_runtime.h>
#include <cuda_bf16.h>
#include <cstdint>

// Problem constants
#define BB 2
#define SS 2048
#define DD 768
#define HH 12
#define DKK 64
#define NT (BB*SS)
#define OUT_OFF ((size_t)BB*SS*DD)

// Scratch
__device__ float g_V[NT*DD];
__device__ float g_ctx[NT*DD];
// Packed split-bf16 Q/K: [token][head][pair(32)] as uint2 {hi bf16x2, lo bf16x2}
__device__ uint4 g_Qp[NT*HH*16];
__device__ uint4 g_Kp[NT*HH*16];

// ---------------------------------------------------------------------------
// helpers
// ---------------------------------------------------------------------------
__device__ __forceinline__ uint32_t tf32r(float x) {
    uint32_t u; asm("cvt.rna.tf32.f32 %0, %1;" : "=r"(u) : "f"(x)); return u;
}
__device__ __forceinline__ float tf32f(float x) { return __uint_as_float(tf32r(x)); }

__device__ __forceinline__ void mma8(float* c,
    uint32_t a0, uint32_t a1, uint32_t a2, uint32_t a3, uint32_t b0, uint32_t b1)
{
    asm volatile(
        "mma.sync.aligned.m16n8k8.row.col.f32.tf32.tf32.f32 "
        "{%0,%1,%2,%3},{%4,%5,%6,%7},{%8,%9},{%0,%1,%2,%3};"
        : "+f"(c[0]), "+f"(c[1]), "+f"(c[2]), "+f"(c[3])
        : "r"(a0), "r"(a1), "r"(a2), "r"(a3), "r"(b0), "r"(b1));
}

__device__ __forceinline__ void mmabf(float* c,
    uint32_t a0, uint32_t a1, uint32_t a2, uint32_t a3, uint32_t b0, uint32_t b1)
{
    asm volatile(
        "mma.sync.aligned.m16n8k16.row.col.f32.bf16.bf16.f32 "
        "{%0,%1,%2,%3},{%4,%5,%6,%7},{%8,%9},{%0,%1,%2,%3};"
        : "+f"(c[0]), "+f"(c[1]), "+f"(c[2]), "+f"(c[3])
        : "r"(a0), "r"(a1), "r"(a2), "r"(a3), "r"(b0), "r"(b1));
}

// split-bf16 pack of (even, odd) element pair: .x = hi word, .y = lo word
__device__ __forceinline__ uint2 splitpack(float e, float o) {
    __nv_bfloat16 he = __float2bfloat16_rn(e), ho = __float2bfloat16_rn(o);
    float re = e - __bfloat162float(he);
    float ro = o - __bfloat162float(ho);
    __nv_bfloat16 le = __float2bfloat16_rn(re), lo = __float2bfloat16_rn(ro);
    uint2 r;
    r.x = (uint32_t)__bfloat16_as_ushort(he) | ((uint32_t)__bfloat16_as_ushort(ho) << 16);
    r.y = (uint32_t)__bfloat16_as_ushort(le) | ((uint32_t)__bfloat16_as_ushort(lo) << 16);
    return r;
}

// ---------------------------------------------------------------------------
// Fused QKV projection: grid (6, 32, 3).
// z=0: query@Wq -> packed Qp    z=1: key@Wk -> packed Kp
// z=2: value@Wv -> float V
// Both paths register-prefetch pipelined.
// ---------------------------------------------------------------------------
__global__ __launch_bounds__(256)
void proj_qkv(const float* __restrict__ q, const float* __restrict__ k,
              const float* __restrict__ v,
              const float* __restrict__ Wq, const float* __restrict__ Wk,
              const float* __restrict__ Wv,
              uint2* __restrict__ Qp, uint2* __restrict__ Kp,
              float* __restrict__ Vout)
{
    __shared__ uint2 Asb[128*8];
    __shared__ uint2 Bsb[128*8];
    __shared__ float Asf[16][132];
    __shared__ float Bsf[16][132];

    const int z = blockIdx.z;
    const float* X = (z == 0) ? q  : (z == 1) ? k  : v;
    const float* W = (z == 0) ? Wq : (z == 1) ? Wk : Wv;

    const int tid  = threadIdx.x;
    const int lane = tid & 31, warp = tid >> 5;
    const int g = lane >> 2, l4 = lane & 3;
    const int wm = warp >> 2, wn = warp & 3;
    const int m0 = blockIdx.y * 128, n0 = blockIdx.x * 128;
    const int K = DD;

    float acc[4][4][4];
#pragma unroll
    for (int i = 0; i < 4; i++)
#pragma unroll
        for (int j = 0; j < 4; j++)
#pragma unroll
            for (int r = 0; r < 4; r++) acc[i][j][r] = 0.f;

    // prefetch tile 0
    float4 pa[2], pbv[2];
#pragma unroll
    for (int i = 0; i < 2; i++) {
        int ii = tid + i * 256;
        int row = ii >> 2, kg = (ii & 3) * 4;
        pa[i]  = *(const float4*)&X[(size_t)(m0 + row) * K + kg];
        pbv[i] = *(const float4*)&W[(size_t)(n0 + row) * K + kg];
    }

    if (z < 2) {
        // ---- split-bf16 path ----
        for (int k0 = 0; k0 < K; k0 += 16) {
#pragma unroll
            for (int i = 0; i < 2; i++) {
                int ii = tid + i * 256;
                int row = ii >> 2, kg = (ii & 3) * 4;
                int p0 = kg >> 1;
                int sw = ((row >> 1) & 1) << 2;
                uint2 wa0 = splitpack(pa[i].x, pa[i].y), wa1 = splitpack(pa[i].z, pa[i].w);
                uint2 wb0 = splitpack(pbv[i].x, pbv[i].y), wb1 = splitpack(pbv[i].z, pbv[i].w);
                *(uint4*)&Asb[row*8 + (p0 ^ sw)] = make_uint4(wa0.x, wa0.y, wa1.x, wa1.y);
                *(uint4*)&Bsb[row*8 + (p0 ^ sw)] = make_uint4(wb0.x, wb0.y, wb1.x, wb1.y);
            }
            __syncthreads();

            if (k0 + 16 < K) {
#pragma unroll
                for (int i = 0; i < 2; i++) {
                    int ii = tid + i * 256;
                    int row = ii >> 2, kg = (ii & 3) * 4;
                    pa[i]  = *(const float4*)&X[(size_t)(m0 + row) * K + k0 + 16 + kg];
                    pbv[i] = *(const float4*)&W[(size_t)(n0 + row) * K + k0 + 16 + kg];
                }
            }

            uint2 bf[4][2];
#pragma unroll
            for (int nt = 0; nt < 4; nt++) {
                int cb = wn * 32 + nt * 8 + g;
                int sb = ((cb >> 1) & 1) << 2;
                bf[nt][0] = Bsb[cb*8 + (l4 ^ sb)];
                bf[nt][1] = Bsb[cb*8 + ((l4 + 4) ^ sb)];
            }
#pragma unroll
            for (int mt = 0; mt < 4; mt++) {
                int r = wm * 64 + mt * 16 + g;
                int sa = ((r >> 1) & 1) << 2;
                uint2 a0 = Asb[r*8 + (l4 ^ sa)];
                uint2 a1 = Asb[(r+8)*8 + (l4 ^ sa)];
                uint2 a2 = Asb[r*8 + ((l4 + 4) ^ sa)];
                uint2 a3 = Asb[(r+8)*8 + ((l4 + 4) ^ sa)];
#pragma unroll
                for (int nt = 0; nt < 4; nt++) {
                    mmabf(acc[mt][nt], a0.x, a1.x, a2.x, a3.x, bf[nt][0].y, bf[nt][1].y);
                    mmabf(acc[mt][nt], a0.y, a1.y, a2.y, a3.y, bf[nt][0].x, bf[nt][1].x);
                    mmabf(acc[mt][nt], a0.x, a1.x, a2.x, a3.x, bf[nt][0].x, bf[nt][1].x);
                }
            }
            __syncthreads();
        }

        uint2* OutPack = (z == 0) ? Qp : Kp;
#pragma unroll
        for (int mt = 0; mt < 4; mt++) {
            int r0 = m0 + wm * 64 + mt * 16 + g;
#pragma unroll
            for (int nt = 0; nt < 4; nt++) {
                int cc = n0 + wn * 32 + nt * 8 + 2 * l4;
                int h = cc >> 6, pg = (cc >> 1) & 31;
                OutPack[((size_t)r0 * HH + h) * 32 + pg] =
                    splitpack(acc[mt][nt][0], acc[mt][nt][1]);
                OutPack[((size_t)(r0 + 8) * HH + h) * 32 + pg] =
                    splitpack(acc[mt][nt][2], acc[mt][nt][3]);
            }
        }
    } else {
        // ---- tf32 path (V projection) ----
        for (int k0 = 0; k0 < K; k0 += 16) {
#pragma unroll
            for (int i = 0; i < 2; i++) {
                int ii = tid + i * 256;
                int row = ii >> 2, kg = (ii & 3) * 4;
                Asf[kg+0][row] = tf32f(pa[i].x);  Asf[kg+1][row] = tf32f(pa[i].y);
                Asf[kg+2][row] = tf32f(pa[i].z);  Asf[kg+3][row] = tf32f(pa[i].w);
                Bsf[kg+0][row] = tf32f(pbv[i].x); Bsf[kg+1][row] = tf32f(pbv[i].y);
                Bsf[kg+2][row] = tf32f(pbv[i].z); Bsf[kg+3][row] = tf32f(pbv[i].w);
            }
            __syncthreads();

            if (k0 + 16 < K) {
#pragma unroll
                for (int i = 0; i < 2; i++) {
                    int ii = tid + i * 256;
                    int row = ii >> 2, kg = (ii & 3) * 4;
                    pa[i]  = *(const float4*)&X[(size_t)(m0 + row) * K + k0 + 16 + kg];
                    pbv[i] = *(const float4*)&W[(size_t)(n0 + row) * K + k0 + 16 + kg];
                }
            }

#pragma unroll
            for (int ks = 0; ks < 2; ks++) {
                uint32_t ah[4][4], bh[4][2];
#pragma unroll
                for (int mt = 0; mt < 4; mt++) {
                    int rb = wm * 64 + mt * 16;
                    ah[mt][0] = __float_as_uint(Asf[ks*8 + l4][rb + g]);
                    ah[mt][1] = __float_as_uint(Asf[ks*8 + l4][rb + g + 8]);
                    ah[mt][2] = __float_as_uint(Asf[ks*8 + l4 + 4][rb + g]);
                    ah[mt][3] = __float_as_uint(Asf[ks*8 + l4 + 4][rb + g + 8]);
                }
#pragma unroll
                for (int nt = 0; nt < 4; nt++) {
                    int cb = wn * 32 + nt * 8;
                    bh[nt][0] = __float_as_uint(Bsf[ks*8 + l4][cb + g]);
                    bh[nt][1] = __float_as_uint(Bsf[ks*8 + l4 + 4][cb + g]);
                }
#pragma unroll
                for (int mt = 0; mt < 4; mt++)
#pragma unroll
                    for (int nt = 0; nt < 4; nt++)
                        mma8(acc[mt][nt], ah[mt][0], ah[mt][1], ah[mt][2], ah[mt][3],
                             bh[nt][0], bh[nt][1]);
            }
            __syncthreads();
        }

#pragma unroll
        for (int mt = 0; mt < 4; mt++) {
            int r0 = m0 + wm * 64 + mt * 16 + g;
#pragma unroll
            for (int nt = 0; nt < 4; nt++) {
                int cc = n0 + wn * 32 + nt * 8 + 2 * l4;
                *(float2*)&Vout[(size_t)r0 * DD + cc] =
                    make_float2(acc[mt][nt][0], acc[mt][nt][1]);
                *(float2*)&Vout[(size_t)(r0 + 8) * DD + cc] =
                    make_float2(acc[mt][nt][2], acc[mt][nt][3]);
            }
        }
    }
}

// ---------------------------------------------------------------------------
// tf32 GEMM (output GEMM), register-prefetch pipelined
// ---------------------------------------------------------------------------
__global__ __launch_bounds__(256)
void gemm_tc(const float* __restrict__ X, const float* __restrict__ W,
             float* __restrict__ C, const float* __restrict__ bias,
             int M, int N, int K)
{
    __shared__ float As[16][132];
    __shared__ float Bs[16][132];

    const int tid  = threadIdx.x;
    const int lane = tid & 31, warp = tid >> 5;
    const int g = lane >> 2, l4 = lane & 3;
    const int wm = warp >> 2, wn = warp & 3;
    const int m0 = blockIdx.y * 128, n0 = blockIdx.x * 128;

    float acc[4][4][4];
#pragma unroll
    for (int i = 0; i < 4; i++)
#pragma unroll
        for (int j = 0; j < 4; j++)
#pragma unroll
            for (int r = 0; r < 4; r++) acc[i][j][r] = 0.f;

    float4 pa[2], pbv[2];
#pragma unroll
    for (int i = 0; i < 2; i++) {
        int ii = tid + i * 256;
        int row = ii >> 2, kg = (ii & 3) * 4;
        pa[i]  = *(const float4*)&X[(size_t)(m0 + row) * K + kg];
        pbv[i] = *(const float4*)&W[(size_t)(n0 + row) * K + kg];
    }

    for (int k0 = 0; k0 < K; k0 += 16) {
#pragma unroll
        for (int i = 0; i < 2; i++) {
            int ii = tid + i * 256;
            int row = ii >> 2, kg = (ii & 3) * 4;
            As[kg+0][row] = tf32f(pa[i].x);  As[kg+1][row] = tf32f(pa[i].y);
            As[kg+2][row] = tf32f(pa[i].z);  As[kg+3][row] = tf32f(pa[i].w);
            Bs[kg+0][row] = tf32f(pbv[i].x); Bs[kg+1][row] = tf32f(pbv[i].y);
            Bs[kg+2][row] = tf32f(pbv[i].z); Bs[kg+3][row] = tf32f(pbv[i].w);
        }
        __syncthreads();

        if (k0 + 16 < K) {
#pragma unroll
            for (int i = 0; i < 2; i++) {
                int ii = tid + i * 256;
                int row = ii >> 2, kg = (ii & 3) * 4;
                pa[i]  = *(const float4*)&X[(size_t)(m0 + row) * K + k0 + 16 + kg];
                pbv[i] = *(const float4*)&W[(size_t)(n0 + row) * K + k0 + 16 + kg];
            }
        }

#pragma unroll
        for (int ks = 0; ks < 2; ks++) {
            uint32_t ah[4][4], bh[4][2];
#pragma unroll
            for (int mt = 0; mt < 4; mt++) {
                int rb = wm * 64 + mt * 16;
                ah[mt][0] = __float_as_uint(As[ks*8 + l4][rb + g]);
                ah[mt][1] = __float_as_uint(As[ks*8 + l4][rb + g + 8]);
                ah[mt][2] = __float_as_uint(As[ks*8 + l4 + 4][rb + g]);
                ah[mt][3] = __float_as_uint(As[ks*8 + l4 + 4][rb + g + 8]);
            }
#pragma unroll
            for (int nt = 0; nt < 4; nt++) {
                int cb = wn * 32 + nt * 8;
                bh[nt][0] = __float_as_uint(Bs[ks*8 + l4][cb + g]);
                bh[nt][1] = __float_as_uint(Bs[ks*8 + l4 + 4][cb + g]);
            }
#pragma unroll
            for (int mt = 0; mt < 4; mt++)
#pragma unroll
                for (int nt = 0; nt < 4; nt++)
                    mma8(acc[mt][nt], ah[mt][0], ah[mt][1], ah[mt][2], ah[mt][3],
                         bh[nt][0], bh[nt][1]);
        }
        __syncthreads();
    }

#pragma unroll
    for (int mt = 0; mt < 4; mt++) {
        int r0 = m0 + wm * 64 + mt * 16 + g;
#pragma unroll
        for (int nt = 0; nt < 4; nt++) {
            int cc = n0 + wn * 32 + nt * 8 + 2 * l4;
            float bx = 0.f, by = 0.f;
            if (bias) { bx = bias[cc]; by = bias[cc + 1]; }
            *(float2*)&C[(size_t)r0 * N + cc] =
                make_float2(acc[mt][nt][0] + bx, acc[mt][nt][1] + by);
            *(float2*)&C[(size_t)(r0 + 8) * N + cc] =
                make_float2(acc[mt][nt][2] + bx, acc[mt][nt][3] + by);
        }
    }
}

// ---------------------------------------------------------------------------
// K1: scores, split-bf16. Block=(qt64, b, h), 256 thr, warps 2(m)x4(n),
// warp tile 32x32, K chunk 128 keys. (round-5 validated shape)
// ---------------------------------------------------------------------------
__global__ __launch_bounds__(256)
void score_bf(const uint2* __restrict__ Qp, const uint2* __restrict__ Kp,
              const int* __restrict__ mask, const float* __restrict__ pb,
              float* __restrict__ Sout)
{
    extern __shared__ uint4 smraw[];
    uint2* sQ = (uint2*)smraw;           // 64*32
    uint2* sK = (uint2*)smraw + 64*32;   // 128*32

    const int tid = threadIdx.x;
    const int lane = tid & 31, w = tid >> 5;
    const int g = lane >> 2, l4 = lane & 3;
    const int wm = w >> 2, wn = w & 3;
    const int qt = blockIdx.x, b = blockIdx.y, h = blockIdx.z;
    const int q0 = qt * 64;

    // stage Q (pure copy, swizzled)
    {
        const uint4* qsrc = (const uint4*)(Qp + ((size_t)(b*SS + q0) * HH + h) * 32);
#pragma unroll
        for (int i = 0; i < 4; i++) {
            int idx = tid + i * 256;          // 1024 uint4
            int row = idx >> 4, p2 = (idx & 15) * 2;
            uint4 v = qsrc[(size_t)row * (HH*16) + (p2 >> 1)];
            int sw = (row & 3) << 2;
            *(uint4*)&sQ[row*32 + (p2 ^ sw)] = v;
        }
    }

    float acc[2][4][4];
#pragma unroll
    for (int mt = 0; mt < 2; mt++)
#pragma unroll
        for (int nt = 0; nt < 4; nt++)
#pragma unroll
            for (int r = 0; r < 4; r++) acc[mt][nt][r] = 0.f;

    for (int kt = 0; kt < SS / 128; kt++) {
        __syncthreads();
        const uint4* ksrc = (const uint4*)(Kp + ((size_t)(b*SS + kt*128) * HH + h) * 32);
#pragma unroll
        for (int i = 0; i < 8; i++) {
            int idx = tid + i * 256;          // 2048 uint4
            int row = idx >> 4, p2 = (idx & 15) * 2;
            uint4 v = ksrc[(size_t)row * (HH*16) + (p2 >> 1)];
            int sw = (row & 3) << 2;
            *(uint4*)&sK[row*32 + (p2 ^ sw)] = v;
        }
        __syncthreads();

#pragma unroll
        for (int s = 0; s < 4; s++) {
            uint2 qa[2][4];
#pragma unroll
            for (int mt = 0; mt < 2; mt++) {
                int r = wm*32 + mt*16 + g;
                int sa = (r & 3) << 2;
                qa[mt][0] = sQ[r*32 + ((8*s + l4) ^ sa)];
                qa[mt][1] = sQ[(r+8)*32 + ((8*s + l4) ^ sa)];
                qa[mt][2] = sQ[r*32 + ((8*s + l4 + 4) ^ sa)];
                qa[mt][3] = sQ[(r+8)*32 + ((8*s + l4 + 4) ^ sa)];
            }
#pragma unroll
            for (int nt = 0; nt < 4; nt++) {
                int key = wn*32 + nt*8 + g;
                int sb = (key & 3) << 2;
                uint2 b0 = sK[key*32 + ((8*s + l4) ^ sb)];
                uint2 b1 = sK[key*32 + ((8*s + l4 + 4) ^ sb)];
#pragma unroll
                for (int mt = 0; mt < 2; mt++) {
                    mmabf(acc[mt][nt], qa[mt][0].x, qa[mt][1].x, qa[mt][2].x, qa[mt][3].x,
                          b0.y, b1.y);
                    mmabf(acc[mt][nt], qa[mt][0].y, qa[mt][1].y, qa[mt][2].y, qa[mt][3].y,
                          b0.x, b1.x);
                    mmabf(acc[mt][nt], qa[mt][0].x, qa[mt][1].x, qa[mt][2].x, qa[mt][3].x,
                          b0.x, b1.x);
                }
            }
        }

        // epilogue for this key chunk
#pragma unroll
        for (int mt = 0; mt < 2; mt++) {
            int r0 = q0 + wm*32 + mt*16 + g;
            int r1 = r0 + 8;
#pragma unroll
            for (int nt = 0; nt < 4; nt++) {
                int col = kt*128 + wn*32 + nt*8 + 2*l4;
                float* a = acc[mt][nt];
                float2 pb0 = *(const float2*)&pb[((size_t)h*SS + r0) * SS + col];
                float2 pb1 = *(const float2*)&pb[((size_t)h*SS + r1) * SS + col];
                int2 mk0 = *(const int2*)&mask[((size_t)b*SS + r0) * SS + col];
                int2 mk1 = *(const int2*)&mask[((size_t)b*SS + r1) * SS + col];
                float2 s0, s1;
                s0.x = a[0] * 0.125f + pb0.x; if (mk0.x == 0) s0.x = -1e9f;
                s0.y = a[1] * 0.125f + pb0.y; if (mk0.y == 0) s0.y = -1e9f;
                s1.x = a[2] * 0.125f + pb1.x; if (mk1.x == 0) s1.x = -1e9f;
                s1.y = a[3] * 0.125f + pb1.y; if (mk1.y == 0) s1.y = -1e9f;
                *(float2*)&Sout[((size_t)(b*HH + h)*SS + r0) * SS + col] = s0;
                *(float2*)&Sout[((size_t)(b*HH + h)*SS + r1) * SS + col] = s1;
                a[0] = 0.f; a[1] = 0.f; a[2] = 0.f; a[3] = 0.f;
            }
        }
    }
}

// ---------------------------------------------------------------------------
// K2: row softmax in place. One 128-thread block per (b,h,q) row.
// ---------------------------------------------------------------------------
__global__ __launch_bounds__(128)
void softmax_kernel(float* __restrict__ S)
{
    __shared__ float red[8];
    const size_t base = (size_t)blockIdx.x * SS;
    const int tid = threadIdx.x;
    const int warp = tid >> 5, lane = tid & 31;

    float4 v[4];
#pragma unroll
    for (int i = 0; i < 4; i++)
        v[i] = *(const float4*)&S[base + i*512 + tid*4];

    float mx = -1e30f;
#pragma unroll
    for (int i = 0; i < 4; i++)
        mx = fmaxf(mx, fmaxf(fmaxf(v[i].x, v[i].y), fmaxf(v[i].z, v[i].w)));
#pragma unroll
    for (int o = 16; o; o >>= 1) mx = fmaxf(mx, __shfl_xor_sync(0xffffffffu, mx, o));
    if (lane == 0) red[warp] = mx;
    __syncthreads();
    mx = fmaxf(fmaxf(red[0], red[1]), fmaxf(red[2], red[3]));

    float sum = 0.f;
#pragma unroll
    for (int i = 0; i < 4; i++) {
        v[i].x = __expf(v[i].x - mx); v[i].y = __expf(v[i].y - mx);
        v[i].z = __expf(v[i].z - mx); v[i].w = __expf(v[i].w - mx);
        sum += (v[i].x + v[i].y) + (v[i].z + v[i].w);
    }
#pragma unroll
    for (int o = 16; o; o >>= 1) sum += __shfl_xor_sync(0xffffffffu, sum, o);
    if (lane == 0) red[4 + warp] = sum;
    __syncthreads();
    sum = (red[4] + red[5]) + (red[6] + red[7]);

    float rinv = 1.f / sum;
#pragma unroll
    for (int i = 0; i < 4; i++) {
        v[i].x *= rinv; v[i].y *= rinv; v[i].z *= rinv; v[i].w *= rinv;
        *(float4*)&S[base + i*512 + tid*4] = v[i];
    }
}

// ---------------------------------------------------------------------------
// K3: ctx = P @ V (tf32). Block=(qt128, b, h), 256 thr, warps 4(m)x2(n).
// ---------------------------------------------------------------------------
#define PSTR 132
#define VSTR 68

__global__ __launch_bounds__(256)
void pv_kernel(const float* __restrict__ P, const float* __restrict__ V,
               float* __restrict__ ctx)
{
    extern __shared__ float sm[];
    float* Ps = sm;                 // 128 * PSTR
    float* Vs = sm + 128 * PSTR;    // 128 * VSTR

    const int tid = threadIdx.x;
    const int lane = tid & 31, w = tid >> 5;
    const int g = lane >> 2, l4 = lane & 3;
    const int wm = w >> 1, wn = w & 1;
    const int qt = blockIdx.x, b = blockIdx.y, h = blockIdx.z;
    const int q0 = qt * 128;

    float acc[2][4][4];
#pragma unroll
    for (int mt = 0; mt < 2; mt++)
#pragma unroll
        for (int nt = 0; nt < 4; nt++)
#pragma unroll
            for (int r = 0; r < 4; r++) acc[mt][nt][r] = 0.f;

    for (int kt = 0; kt < SS / 128; kt++) {
        __syncthreads();
#pragma unroll
        for (int i = 0; i < 16; i++) {
            int idx = tid + i * 256;
            int row = idx >> 5, c4 = (idx & 31) * 4;
            float4 v = *(const float4*)&P[((size_t)(b*HH + h)*SS + q0 + row) * SS + kt*128 + c4];
            v.x = tf32f(v.x); v.y = tf32f(v.y); v.z = tf32f(v.z); v.w = tf32f(v.w);
            *(float4*)&Ps[row * PSTR + c4] = v;
        }
#pragma unroll
        for (int i = 0; i < 8; i++) {
            int idx = tid + i * 256;
            int row = idx >> 4, c4 = (idx & 15) * 4;
            float4 v = *(const float4*)&V[(size_t)(b*SS + kt*128 + row) * DD + h*DKK + c4];
            v.x = tf32f(v.x); v.y = tf32f(v.y); v.z = tf32f(v.z); v.w = tf32f(v.w);
            *(float4*)&Vs[row * VSTR + c4] = v;
        }
        __syncthreads();

#pragma unroll
        for (int ks = 0; ks < 16; ks++) {
            uint32_t a[2][4];
#pragma unroll
            for (int mt = 0; mt < 2; mt++) {
                int r = wm*32 + mt*16 + g;
                a[mt][0] = __float_as_uint(Ps[r * PSTR + ks*8 + l4]);
                a[mt][1] = __float_as_uint(Ps[(r+8) * PSTR + ks*8 + l4]);
                a[mt][2] = __float_as_uint(Ps[r * PSTR + ks*8 + l4 + 4]);
                a[mt][3] = __float_as_uint(Ps[(r+8) * PSTR + ks*8 + l4 + 4]);
            }
#pragma unroll
            for (int nt = 0; nt < 4; nt++) {
                int col = wn*32 + nt*8 + g;
                uint32_t b0 = __float_as_uint(Vs[(ks*8 + l4) * VSTR + col]);
                uint32_t b1 = __float_as_uint(Vs[(ks*8 + l4 + 4) * VSTR + col]);
#pragma unroll
                for (int mt = 0; mt < 2; mt++)
                    mma8(acc[mt][nt], a[mt][0], a[mt][1], a[mt][2], a[mt][3], b0, b1);
            }
        }
    }

#pragma unroll
    for (int mt = 0; mt < 2; mt++) {
        int r0 = q0 + wm*32 + mt*16 + g;
#pragma unroll
        for (int nt = 0; nt < 4; nt++) {
            int cc = h*DKK + wn*32 + nt*8 + 2*l4;
            *(float2*)&ctx[(size_t)(b*SS + r0) * DD + cc] =
                make_float2(acc[mt][nt][0], acc[mt][nt][1]);
            *(float2*)&ctx[(size_t)(b*SS + r0 + 8) * DD + cc] =
                make_float2(acc[mt][nt][2], acc[mt][nt][3]);
        }
    }
}

// ---------------------------------------------------------------------------
// Launch
// ---------------------------------------------------------------------------
extern "C" void kernel_launch(void* const* d_in, const int* in_sizes, int n_in,
                              void* d_out, int out_size)
{
    const float* query = (const float*)d_in[0];
    const float* key   = (const float*)d_in[1];
    const float* value = (const float*)d_in[2];
    const int*   mask  = (const int*)  d_in[3];
    const float* pb    = (const float*)d_in[4];
    const float* Wq    = (const float*)d_in[5];
    const float* Wk    = (const float*)d_in[6];
    const float* Wv    = (const float*)d_in[7];
    const float* Wo    = (const float*)d_in[8];
    const float* bo    = (const float*)d_in[9];
    float* out = (float*)d_out;
    float* attn = out + OUT_OFF;

    float *pV, *pC;
    uint4 *pQp, *pKp;
    cudaGetSymbolAddress((void**)&pV,  g_V);
    cudaGetSymbolAddress((void**)&pC,  g_ctx);
    cudaGetSymbolAddress((void**)&pQp, g_Qp);
    cudaGetSymbolAddress((void**)&pKp, g_Kp);

    const int SC_SMEM = (64*32 + 128*32) * sizeof(uint2);            // 49152
    const int PV_SMEM = (128*PSTR + 128*VSTR) * sizeof(float);       // 102400
    cudaFuncSetAttribute(score_bf,
                         cudaFuncAttributeMaxDynamicSharedMemorySize, SC_SMEM);
    cudaFuncSetAttribute(pv_kernel,
                         cudaFuncAttributeMaxDynamicSharedMemorySize, PV_SMEM);

    dim3 gq(DD / 128, NT / 128, 3);   // (6, 32, 3) — fused QKV projections
    proj_qkv<<<gq, 256>>>(query, key, value, Wq, Wk, Wv,
                          (uint2*)pQp, (uint2*)pKp, pV);

    dim3 gs(SS / 64, BB, HH);      // (32, 2, 12) — h slowest for L2 reuse
    score_bf<<<gs, 256, SC_SMEM>>>((const uint2*)pQp, (const uint2*)pKp,
                                   mask, pb, attn);

    softmax_kernel<<<BB * HH * SS, 128>>>(attn);

    dim3 gp(SS / 128, BB, HH);     // (16, 2, 12)
    pv_kernel<<<gp, 256, PV_SMEM>>>(attn, pV, pC);

    dim3 gg(DD / 128, NT / 128);   // (6, 32)
    gemm_tc<<<gg, 256>>>(pC, Wo, out, bo, NT, DD, DD);
}

// round 14
// speedup vs baseline: 1.5199x; 1.0475x over previous
#include <cuda_runtime.h>
#include <cuda_bf16.h>
#include <cstdint>

// Problem constants
#define BB 2
#define SS 2048
#define DD 768
#define HH 12
#define DKK 64
#define NT (BB*SS)
#define OUT_OFF ((size_t)BB*SS*DD)

// Scratch
__device__ float g_V[NT*DD];
__device__ float g_ctx[NT*DD];
// Packed split-bf16 Q/K: [token][head][pair(32)] as uint2 {hi bf16x2, lo bf16x2}
__device__ uint4 g_Qp[NT*HH*16];
__device__ uint4 g_Kp[NT*HH*16];

// ---------------------------------------------------------------------------
// helpers
// ---------------------------------------------------------------------------
__device__ __forceinline__ uint32_t tf32r(float x) {
    uint32_t u; asm("cvt.rna.tf32.f32 %0, %1;" : "=r"(u) : "f"(x)); return u;
}
__device__ __forceinline__ float tf32f(float x) { return __uint_as_float(tf32r(x)); }

__device__ __forceinline__ void mma8(float* c,
    uint32_t a0, uint32_t a1, uint32_t a2, uint32_t a3, uint32_t b0, uint32_t b1)
{
    asm volatile(
        "mma.sync.aligned.m16n8k8.row.col.f32.tf32.tf32.f32 "
        "{%0,%1,%2,%3},{%4,%5,%6,%7},{%8,%9},{%0,%1,%2,%3};"
        : "+f"(c[0]), "+f"(c[1]), "+f"(c[2]), "+f"(c[3])
        : "r"(a0), "r"(a1), "r"(a2), "r"(a3), "r"(b0), "r"(b1));
}

__device__ __forceinline__ void mmabf(float* c,
    uint32_t a0, uint32_t a1, uint32_t a2, uint32_t a3, uint32_t b0, uint32_t b1)
{
    asm volatile(
        "mma.sync.aligned.m16n8k16.row.col.f32.bf16.bf16.f32 "
        "{%0,%1,%2,%3},{%4,%5,%6,%7},{%8,%9},{%0,%1,%2,%3};"
        : "+f"(c[0]), "+f"(c[1]), "+f"(c[2]), "+f"(c[3])
        : "r"(a0), "r"(a1), "r"(a2), "r"(a3), "r"(b0), "r"(b1));
}

// split-bf16 pack of (even, odd) element pair: .x = hi word, .y = lo word
__device__ __forceinline__ uint2 splitpack(float e, float o) {
    __nv_bfloat16 he = __float2bfloat16_rn(e), ho = __float2bfloat16_rn(o);
    float re = e - __bfloat162float(he);
    float ro = o - __bfloat162float(ho);
    __nv_bfloat16 le = __float2bfloat16_rn(re), lo = __float2bfloat16_rn(ro);
    uint2 r;
    r.x = (uint32_t)__bfloat16_as_ushort(he) | ((uint32_t)__bfloat16_as_ushort(ho) << 16);
    r.y = (uint32_t)__bfloat16_as_ushort(le) | ((uint32_t)__bfloat16_as_ushort(lo) << 16);
    return r;
}

// ---------------------------------------------------------------------------
// Fused QKV projection: grid (6, 32, 3).
// z=0: query@Wq -> packed Qp    z=1: key@Wk -> packed Kp
// z=2: value@Wv -> float V
// Both paths register-prefetch pipelined.
// ---------------------------------------------------------------------------
__global__ __launch_bounds__(256)
void proj_qkv(const float* __restrict__ q, const float* __restrict__ k,
              const float* __restrict__ v,
              const float* __restrict__ Wq, const float* __restrict__ Wk,
              const float* __restrict__ Wv,
              uint2* __restrict__ Qp, uint2* __restrict__ Kp,
              float* __restrict__ Vout)
{
    __shared__ uint2 Asb[128*8];
    __shared__ uint2 Bsb[128*8];
    __shared__ float Asf[16][132];
    __shared__ float Bsf[16][132];

    const int z = blockIdx.z;
    const float* X = (z == 0) ? q  : (z == 1) ? k  : v;
    const float* W = (z == 0) ? Wq : (z == 1) ? Wk : Wv;

    const int tid  = threadIdx.x;
    const int lane = tid & 31, warp = tid >> 5;
    const int g = lane >> 2, l4 = lane & 3;
    const int wm = warp >> 2, wn = warp & 3;
    const int m0 = blockIdx.y * 128, n0 = blockIdx.x * 128;
    const int K = DD;

    float acc[4][4][4];
#pragma unroll
    for (int i = 0; i < 4; i++)
#pragma unroll
        for (int j = 0; j < 4; j++)
#pragma unroll
            for (int r = 0; r < 4; r++) acc[i][j][r] = 0.f;

    // prefetch tile 0
    float4 pa[2], pbv[2];
#pragma unroll
    for (int i = 0; i < 2; i++) {
        int ii = tid + i * 256;
        int row = ii >> 2, kg = (ii & 3) * 4;
        pa[i]  = *(const float4*)&X[(size_t)(m0 + row) * K + kg];
        pbv[i] = *(const float4*)&W[(size_t)(n0 + row) * K + kg];
    }

    if (z < 2) {
        // ---- split-bf16 path ----
        for (int k0 = 0; k0 < K; k0 += 16) {
#pragma unroll
            for (int i = 0; i < 2; i++) {
                int ii = tid + i * 256;
                int row = ii >> 2, kg = (ii & 3) * 4;
                int p0 = kg >> 1;
                int sw = ((row >> 1) & 1) << 2;
                uint2 wa0 = splitpack(pa[i].x, pa[i].y), wa1 = splitpack(pa[i].z, pa[i].w);
                uint2 wb0 = splitpack(pbv[i].x, pbv[i].y), wb1 = splitpack(pbv[i].z, pbv[i].w);
                *(uint4*)&Asb[row*8 + (p0 ^ sw)] = make_uint4(wa0.x, wa0.y, wa1.x, wa1.y);
                *(uint4*)&Bsb[row*8 + (p0 ^ sw)] = make_uint4(wb0.x, wb0.y, wb1.x, wb1.y);
            }
            __syncthreads();

            if (k0 + 16 < K) {
#pragma unroll
                for (int i = 0; i < 2; i++) {
                    int ii = tid + i * 256;
                    int row = ii >> 2, kg = (ii & 3) * 4;
                    pa[i]  = *(const float4*)&X[(size_t)(m0 + row) * K + k0 + 16 + kg];
                    pbv[i] = *(const float4*)&W[(size_t)(n0 + row) * K + k0 + 16 + kg];
                }
            }

            uint2 bf[4][2];
#pragma unroll
            for (int nt = 0; nt < 4; nt++) {
                int cb = wn * 32 + nt * 8 + g;
                int sb = ((cb >> 1) & 1) << 2;
                bf[nt][0] = Bsb[cb*8 + (l4 ^ sb)];
                bf[nt][1] = Bsb[cb*8 + ((l4 + 4) ^ sb)];
            }
#pragma unroll
            for (int mt = 0; mt < 4; mt++) {
                int r = wm * 64 + mt * 16 + g;
                int sa = ((r >> 1) & 1) << 2;
                uint2 a0 = Asb[r*8 + (l4 ^ sa)];
                uint2 a1 = Asb[(r+8)*8 + (l4 ^ sa)];
                uint2 a2 = Asb[r*8 + ((l4 + 4) ^ sa)];
                uint2 a3 = Asb[(r+8)*8 + ((l4 + 4) ^ sa)];
#pragma unroll
                for (int nt = 0; nt < 4; nt++) {
                    mmabf(acc[mt][nt], a0.x, a1.x, a2.x, a3.x, bf[nt][0].y, bf[nt][1].y);
                    mmabf(acc[mt][nt], a0.y, a1.y, a2.y, a3.y, bf[nt][0].x, bf[nt][1].x);
                    mmabf(acc[mt][nt], a0.x, a1.x, a2.x, a3.x, bf[nt][0].x, bf[nt][1].x);
                }
            }
            __syncthreads();
        }

        uint2* OutPack = (z == 0) ? Qp : Kp;
#pragma unroll
        for (int mt = 0; mt < 4; mt++) {
            int r0 = m0 + wm * 64 + mt * 16 + g;
#pragma unroll
            for (int nt = 0; nt < 4; nt++) {
                int cc = n0 + wn * 32 + nt * 8 + 2 * l4;
                int h = cc >> 6, pg = (cc >> 1) & 31;
                OutPack[((size_t)r0 * HH + h) * 32 + pg] =
                    splitpack(acc[mt][nt][0], acc[mt][nt][1]);
                OutPack[((size_t)(r0 + 8) * HH + h) * 32 + pg] =
                    splitpack(acc[mt][nt][2], acc[mt][nt][3]);
            }
        }
    } else {
        // ---- tf32 path (V projection) ----
        for (int k0 = 0; k0 < K; k0 += 16) {
#pragma unroll
            for (int i = 0; i < 2; i++) {
                int ii = tid + i * 256;
                int row = ii >> 2, kg = (ii & 3) * 4;
                Asf[kg+0][row] = tf32f(pa[i].x);  Asf[kg+1][row] = tf32f(pa[i].y);
                Asf[kg+2][row] = tf32f(pa[i].z);  Asf[kg+3][row] = tf32f(pa[i].w);
                Bsf[kg+0][row] = tf32f(pbv[i].x); Bsf[kg+1][row] = tf32f(pbv[i].y);
                Bsf[kg+2][row] = tf32f(pbv[i].z); Bsf[kg+3][row] = tf32f(pbv[i].w);
            }
            __syncthreads();

            if (k0 + 16 < K) {
#pragma unroll
                for (int i = 0; i < 2; i++) {
                    int ii = tid + i * 256;
                    int row = ii >> 2, kg = (ii & 3) * 4;
                    pa[i]  = *(const float4*)&X[(size_t)(m0 + row) * K + k0 + 16 + kg];
                    pbv[i] = *(const float4*)&W[(size_t)(n0 + row) * K + k0 + 16 + kg];
                }
            }

#pragma unroll
            for (int ks = 0; ks < 2; ks++) {
                uint32_t ah[4][4], bh[4][2];
#pragma unroll
                for (int mt = 0; mt < 4; mt++) {
                    int rb = wm * 64 + mt * 16;
                    ah[mt][0] = __float_as_uint(Asf[ks*8 + l4][rb + g]);
                    ah[mt][1] = __float_as_uint(Asf[ks*8 + l4][rb + g + 8]);
                    ah[mt][2] = __float_as_uint(Asf[ks*8 + l4 + 4][rb + g]);
                    ah[mt][3] = __float_as_uint(Asf[ks*8 + l4 + 4][rb + g + 8]);
                }
#pragma unroll
                for (int nt = 0; nt < 4; nt++) {
                    int cb = wn * 32 + nt * 8;
                    bh[nt][0] = __float_as_uint(Bsf[ks*8 + l4][cb + g]);
                    bh[nt][1] = __float_as_uint(Bsf[ks*8 + l4 + 4][cb + g]);
                }
#pragma unroll
                for (int mt = 0; mt < 4; mt++)
#pragma unroll
                    for (int nt = 0; nt < 4; nt++)
                        mma8(acc[mt][nt], ah[mt][0], ah[mt][1], ah[mt][2], ah[mt][3],
                             bh[nt][0], bh[nt][1]);
            }
            __syncthreads();
        }

#pragma unroll
        for (int mt = 0; mt < 4; mt++) {
            int r0 = m0 + wm * 64 + mt * 16 + g;
#pragma unroll
            for (int nt = 0; nt < 4; nt++) {
                int cc = n0 + wn * 32 + nt * 8 + 2 * l4;
                *(float2*)&Vout[(size_t)r0 * DD + cc] =
                    make_float2(acc[mt][nt][0], acc[mt][nt][1]);
                *(float2*)&Vout[(size_t)(r0 + 8) * DD + cc] =
                    make_float2(acc[mt][nt][2], acc[mt][nt][3]);
            }
        }
    }
}

// ---------------------------------------------------------------------------
// tf32 GEMM (output GEMM), register-prefetch pipelined
// ---------------------------------------------------------------------------
__global__ __launch_bounds__(256)
void gemm_tc(const float* __restrict__ X, const float* __restrict__ W,
             float* __restrict__ C, const float* __restrict__ bias,
             int M, int N, int K)
{
    __shared__ float As[16][132];
    __shared__ float Bs[16][132];

    const int tid  = threadIdx.x;
    const int lane = tid & 31, warp = tid >> 5;
    const int g = lane >> 2, l4 = lane & 3;
    const int wm = warp >> 2, wn = warp & 3;
    const int m0 = blockIdx.y * 128, n0 = blockIdx.x * 128;

    float acc[4][4][4];
#pragma unroll
    for (int i = 0; i < 4; i++)
#pragma unroll
        for (int j = 0; j < 4; j++)
#pragma unroll
            for (int r = 0; r < 4; r++) acc[i][j][r] = 0.f;

    float4 pa[2], pbv[2];
#pragma unroll
    for (int i = 0; i < 2; i++) {
        int ii = tid + i * 256;
        int row = ii >> 2, kg = (ii & 3) * 4;
        pa[i]  = *(const float4*)&X[(size_t)(m0 + row) * K + kg];
        pbv[i] = *(const float4*)&W[(size_t)(n0 + row) * K + kg];
    }

    for (int k0 = 0; k0 < K; k0 += 16) {
#pragma unroll
        for (int i = 0; i < 2; i++) {
            int ii = tid + i * 256;
            int row = ii >> 2, kg = (ii & 3) * 4;
            As[kg+0][row] = tf32f(pa[i].x);  As[kg+1][row] = tf32f(pa[i].y);
            As[kg+2][row] = tf32f(pa[i].z);  As[kg+3][row] = tf32f(pa[i].w);
            Bs[kg+0][row] = tf32f(pbv[i].x); Bs[kg+1][row] = tf32f(pbv[i].y);
            Bs[kg+2][row] = tf32f(pbv[i].z); Bs[kg+3][row] = tf32f(pbv[i].w);
        }
        __syncthreads();

        if (k0 + 16 < K) {
#pragma unroll
            for (int i = 0; i < 2; i++) {
                int ii = tid + i * 256;
                int row = ii >> 2, kg = (ii & 3) * 4;
                pa[i]  = *(const float4*)&X[(size_t)(m0 + row) * K + k0 + 16 + kg];
                pbv[i] = *(const float4*)&W[(size_t)(n0 + row) * K + k0 + 16 + kg];
            }
        }

#pragma unroll
        for (int ks = 0; ks < 2; ks++) {
            uint32_t ah[4][4], bh[4][2];
#pragma unroll
            for (int mt = 0; mt < 4; mt++) {
                int rb = wm * 64 + mt * 16;
                ah[mt][0] = __float_as_uint(As[ks*8 + l4][rb + g]);
                ah[mt][1] = __float_as_uint(As[ks*8 + l4][rb + g + 8]);
                ah[mt][2] = __float_as_uint(As[ks*8 + l4 + 4][rb + g]);
                ah[mt][3] = __float_as_uint(As[ks*8 + l4 + 4][rb + g + 8]);
            }
#pragma unroll
            for (int nt = 0; nt < 4; nt++) {
                int cb = wn * 32 + nt * 8;
                bh[nt][0] = __float_as_uint(Bs[ks*8 + l4][cb + g]);
                bh[nt][1] = __float_as_uint(Bs[ks*8 + l4 + 4][cb + g]);
            }
#pragma unroll
            for (int mt = 0; mt < 4; mt++)
#pragma unroll
                for (int nt = 0; nt < 4; nt++)
                    mma8(acc[mt][nt], ah[mt][0], ah[mt][1], ah[mt][2], ah[mt][3],
                         bh[nt][0], bh[nt][1]);
        }
        __syncthreads();
    }

#pragma unroll
    for (int mt = 0; mt < 4; mt++) {
        int r0 = m0 + wm * 64 + mt * 16 + g;
#pragma unroll
        for (int nt = 0; nt < 4; nt++) {
            int cc = n0 + wn * 32 + nt * 8 + 2 * l4;
            float bx = 0.f, by = 0.f;
            if (bias) { bx = bias[cc]; by = bias[cc + 1]; }
            *(float2*)&C[(size_t)r0 * N + cc] =
                make_float2(acc[mt][nt][0] + bx, acc[mt][nt][1] + by);
            *(float2*)&C[(size_t)(r0 + 8) * N + cc] =
                make_float2(acc[mt][nt][2] + bx, acc[mt][nt][3] + by);
        }
    }
}

// ---------------------------------------------------------------------------
// K1: scores, split-bf16. Block=(qt64, b, h), 256 thr, warps 2(m)x4(n),
// warp tile 32x32, K chunk 128 keys. (round-5 validated shape)
// ---------------------------------------------------------------------------
__global__ __launch_bounds__(256)
void score_bf(const uint2* __restrict__ Qp, const uint2* __restrict__ Kp,
              const int* __restrict__ mask, const float* __restrict__ pb,
              float* __restrict__ Sout)
{
    extern __shared__ uint4 smraw[];
    uint2* sQ = (uint2*)smraw;           // 64*32
    uint2* sK = (uint2*)smraw + 64*32;   // 128*32

    const int tid = threadIdx.x;
    const int lane = tid & 31, w = tid >> 5;
    const int g = lane >> 2, l4 = lane & 3;
    const int wm = w >> 2, wn = w & 3;
    const int qt = blockIdx.x, b = blockIdx.y, h = blockIdx.z;
    const int q0 = qt * 64;

    // stage Q (pure copy, swizzled)
    {
        const uint4* qsrc = (const uint4*)(Qp + ((size_t)(b*SS + q0) * HH + h) * 32);
#pragma unroll
        for (int i = 0; i < 4; i++) {
            int idx = tid + i * 256;          // 1024 uint4
            int row = idx >> 4, p2 = (idx & 15) * 2;
            uint4 v = qsrc[(size_t)row * (HH*16) + (p2 >> 1)];
            int sw = (row & 3) << 2;
            *(uint4*)&sQ[row*32 + (p2 ^ sw)] = v;
        }
    }

    float acc[2][4][4];
#pragma unroll
    for (int mt = 0; mt < 2; mt++)
#pragma unroll
        for (int nt = 0; nt < 4; nt++)
#pragma unroll
            for (int r = 0; r < 4; r++) acc[mt][nt][r] = 0.f;

    for (int kt = 0; kt < SS / 128; kt++) {
        __syncthreads();
        const uint4* ksrc = (const uint4*)(Kp + ((size_t)(b*SS + kt*128) * HH + h) * 32);
#pragma unroll
        for (int i = 0; i < 8; i++) {
            int idx = tid + i * 256;          // 2048 uint4
            int row = idx >> 4, p2 = (idx & 15) * 2;
            uint4 v = ksrc[(size_t)row * (HH*16) + (p2 >> 1)];
            int sw = (row & 3) << 2;
            *(uint4*)&sK[row*32 + (p2 ^ sw)] = v;
        }
        __syncthreads();

#pragma unroll
        for (int s = 0; s < 4; s++) {
            uint2 qa[2][4];
#pragma unroll
            for (int mt = 0; mt < 2; mt++) {
                int r = wm*32 + mt*16 + g;
                int sa = (r & 3) << 2;
                qa[mt][0] = sQ[r*32 + ((8*s + l4) ^ sa)];
                qa[mt][1] = sQ[(r+8)*32 + ((8*s + l4) ^ sa)];
                qa[mt][2] = sQ[r*32 + ((8*s + l4 + 4) ^ sa)];
                qa[mt][3] = sQ[(r+8)*32 + ((8*s + l4 + 4) ^ sa)];
            }
#pragma unroll
            for (int nt = 0; nt < 4; nt++) {
                int key = wn*32 + nt*8 + g;
                int sb = (key & 3) << 2;
                uint2 b0 = sK[key*32 + ((8*s + l4) ^ sb)];
                uint2 b1 = sK[key*32 + ((8*s + l4 + 4) ^ sb)];
#pragma unroll
                for (int mt = 0; mt < 2; mt++) {
                    mmabf(acc[mt][nt], qa[mt][0].x, qa[mt][1].x, qa[mt][2].x, qa[mt][3].x,
                          b0.y, b1.y);
                    mmabf(acc[mt][nt], qa[mt][0].y, qa[mt][1].y, qa[mt][2].y, qa[mt][3].y,
                          b0.x, b1.x);
                    mmabf(acc[mt][nt], qa[mt][0].x, qa[mt][1].x, qa[mt][2].x, qa[mt][3].x,
                          b0.x, b1.x);
                }
            }
        }

        // epilogue for this key chunk
#pragma unroll
        for (int mt = 0; mt < 2; mt++) {
            int r0 = q0 + wm*32 + mt*16 + g;
            int r1 = r0 + 8;
#pragma unroll
            for (int nt = 0; nt < 4; nt++) {
                int col = kt*128 + wn*32 + nt*8 + 2*l4;
                float* a = acc[mt][nt];
                float2 pb0 = *(const float2*)&pb[((size_t)h*SS + r0) * SS + col];
                float2 pb1 = *(const float2*)&pb[((size_t)h*SS + r1) * SS + col];
                int2 mk0 = *(const int2*)&mask[((size_t)b*SS + r0) * SS + col];
                int2 mk1 = *(const int2*)&mask[((size_t)b*SS + r1) * SS + col];
                float2 s0, s1;
                s0.x = a[0] * 0.125f + pb0.x; if (mk0.x == 0) s0.x = -1e9f;
                s0.y = a[1] * 0.125f + pb0.y; if (mk0.y == 0) s0.y = -1e9f;
                s1.x = a[2] * 0.125f + pb1.x; if (mk1.x == 0) s1.x = -1e9f;
                s1.y = a[3] * 0.125f + pb1.y; if (mk1.y == 0) s1.y = -1e9f;
                *(float2*)&Sout[((size_t)(b*HH + h)*SS + r0) * SS + col] = s0;
                *(float2*)&Sout[((size_t)(b*HH + h)*SS + r1) * SS + col] = s1;
                a[0] = 0.f; a[1] = 0.f; a[2] = 0.f; a[3] = 0.f;
            }
        }
    }
}

// ---------------------------------------------------------------------------
// K2: row softmax in place. One 128-thread block per (b,h,q) row.
// ---------------------------------------------------------------------------
__global__ __launch_bounds__(128)
void softmax_kernel(float* __restrict__ S)
{
    __shared__ float red[8];
    const size_t base = (size_t)blockIdx.x * SS;
    const int tid = threadIdx.x;
    const int warp = tid >> 5, lane = tid & 31;

    float4 v[4];
#pragma unroll
    for (int i = 0; i < 4; i++)
        v[i] = *(const float4*)&S[base + i*512 + tid*4];

    float mx = -1e30f;
#pragma unroll
    for (int i = 0; i < 4; i++)
        mx = fmaxf(mx, fmaxf(fmaxf(v[i].x, v[i].y), fmaxf(v[i].z, v[i].w)));
#pragma unroll
    for (int o = 16; o; o >>= 1) mx = fmaxf(mx, __shfl_xor_sync(0xffffffffu, mx, o));
    if (lane == 0) red[warp] = mx;
    __syncthreads();
    mx = fmaxf(fmaxf(red[0], red[1]), fmaxf(red[2], red[3]));

    float sum = 0.f;
#pragma unroll
    for (int i = 0; i < 4; i++) {
        v[i].x = __expf(v[i].x - mx); v[i].y = __expf(v[i].y - mx);
        v[i].z = __expf(v[i].z - mx); v[i].w = __expf(v[i].w - mx);
        sum += (v[i].x + v[i].y) + (v[i].z + v[i].w);
    }
#pragma unroll
    for (int o = 16; o; o >>= 1) sum += __shfl_xor_sync(0xffffffffu, sum, o);
    if (lane == 0) red[4 + warp] = sum;
    __syncthreads();
    sum = (red[4] + red[5]) + (red[6] + red[7]);

    float rinv = 1.f / sum;
#pragma unroll
    for (int i = 0; i < 4; i++) {
        v[i].x *= rinv; v[i].y *= rinv; v[i].z *= rinv; v[i].w *= rinv;
        *(float4*)&S[base + i*512 + tid*4] = v[i];
    }
}

// ---------------------------------------------------------------------------
// K3: ctx = P @ V (tf32). Block=(qt64, b, h), 256 thr, warps 2(m)x4(n),
// warp tile 32x16. 68.6KB smem -> 3 blocks/SM for latency hiding.
// ---------------------------------------------------------------------------
#define PSTR 132
#define VSTR 68

__global__ __launch_bounds__(256, 3)
void pv_kernel(const float* __restrict__ P, const float* __restrict__ V,
               float* __restrict__ ctx)
{
    extern __shared__ float sm[];
    float* Ps = sm;                 // 64 * PSTR
    float* Vs = sm + 64 * PSTR;     // 128 * VSTR

    const int tid = threadIdx.x;
    const int lane = tid & 31, w = tid >> 5;
    const int g = lane >> 2, l4 = lane & 3;
    const int wm = w >> 2, wn = w & 3;    // 2(m) x 4(n)
    const int qt = blockIdx.x, b = blockIdx.y, h = blockIdx.z;
    const int q0 = qt * 64;

    float acc[2][2][4];
#pragma unroll
    for (int mt = 0; mt < 2; mt++)
#pragma unroll
        for (int nt = 0; nt < 2; nt++)
#pragma unroll
            for (int r = 0; r < 4; r++) acc[mt][nt][r] = 0.f;

    for (int kt = 0; kt < SS / 128; kt++) {
        __syncthreads();
        // stage P: 64 rows x 128 cols
#pragma unroll
        for (int i = 0; i < 8; i++) {
            int idx = tid + i * 256;
            int row = idx >> 5, c4 = (idx & 31) * 4;
            float4 v = *(const float4*)&P[((size_t)(b*HH + h)*SS + q0 + row) * SS + kt*128 + c4];
            v.x = tf32f(v.x); v.y = tf32f(v.y); v.z = tf32f(v.z); v.w = tf32f(v.w);
            *(float4*)&Ps[row * PSTR + c4] = v;
        }
        // stage V: 128 rows x 64 cols
#pragma unroll
        for (int i = 0; i < 8; i++) {
            int idx = tid + i * 256;
            int row = idx >> 4, c4 = (idx & 15) * 4;
            float4 v = *(const float4*)&V[(size_t)(b*SS + kt*128 + row) * DD + h*DKK + c4];
            v.x = tf32f(v.x); v.y = tf32f(v.y); v.z = tf32f(v.z); v.w = tf32f(v.w);
            *(float4*)&Vs[row * VSTR + c4] = v;
        }
        __syncthreads();

#pragma unroll
        for (int ks = 0; ks < 16; ks++) {
            uint32_t a[2][4];
#pragma unroll
            for (int mt = 0; mt < 2; mt++) {
                int r = wm*32 + mt*16 + g;
                a[mt][0] = __float_as_uint(Ps[r * PSTR + ks*8 + l4]);
                a[mt][1] = __float_as_uint(Ps[(r+8) * PSTR + ks*8 + l4]);
                a[mt][2] = __float_as_uint(Ps[r * PSTR + ks*8 + l4 + 4]);
                a[mt][3] = __float_as_uint(Ps[(r+8) * PSTR + ks*8 + l4 + 4]);
            }
#pragma unroll
            for (int nt = 0; nt < 2; nt++) {
                int col = wn*16 + nt*8 + g;
                uint32_t b0 = __float_as_uint(Vs[(ks*8 + l4) * VSTR + col]);
                uint32_t b1 = __float_as_uint(Vs[(ks*8 + l4 + 4) * VSTR + col]);
#pragma unroll
                for (int mt = 0; mt < 2; mt++)
                    mma8(acc[mt][nt], a[mt][0], a[mt][1], a[mt][2], a[mt][3], b0, b1);
            }
        }
    }

#pragma unroll
    for (int mt = 0; mt < 2; mt++) {
        int r0 = q0 + wm*32 + mt*16 + g;
#pragma unroll
        for (int nt = 0; nt < 2; nt++) {
            int cc = h*DKK + wn*16 + nt*8 + 2*l4;
            *(float2*)&ctx[(size_t)(b*SS + r0) * DD + cc] =
                make_float2(acc[mt][nt][0], acc[mt][nt][1]);
            *(float2*)&ctx[(size_t)(b*SS + r0 + 8) * DD + cc] =
                make_float2(acc[mt][nt][2], acc[mt][nt][3]);
        }
    }
}

// ---------------------------------------------------------------------------
// Launch
// ---------------------------------------------------------------------------
extern "C" void kernel_launch(void* const* d_in, const int* in_sizes, int n_in,
                              void* d_out, int out_size)
{
    const float* query = (const float*)d_in[0];
    const float* key   = (const float*)d_in[1];
    const float* value = (const float*)d_in[2];
    const int*   mask  = (const int*)  d_in[3];
    const float* pb    = (const float*)d_in[4];
    const float* Wq    = (const float*)d_in[5];
    const float* Wk    = (const float*)d_in[6];
    const float* Wv    = (const float*)d_in[7];
    const float* Wo    = (const float*)d_in[8];
    const float* bo    = (const float*)d_in[9];
    float* out = (float*)d_out;
    float* attn = out + OUT_OFF;

    float *pV, *pC;
    uint4 *pQp, *pKp;
    cudaGetSymbolAddress((void**)&pV,  g_V);
    cudaGetSymbolAddress((void**)&pC,  g_ctx);
    cudaGetSymbolAddress((void**)&pQp, g_Qp);
    cudaGetSymbolAddress((void**)&pKp, g_Kp);

    const int SC_SMEM = (64*32 + 128*32) * sizeof(uint2);            // 49152
    const int PV_SMEM = (64*PSTR + 128*VSTR) * sizeof(float);        // 68608
    cudaFuncSetAttribute(score_bf,
                         cudaFuncAttributeMaxDynamicSharedMemorySize, SC_SMEM);
    cudaFuncSetAttribute(pv_kernel,
                         cudaFuncAttributeMaxDynamicSharedMemorySize, PV_SMEM);

    dim3 gq(DD / 128, NT / 128, 3);   // (6, 32, 3) — fused QKV projections
    proj_qkv<<<gq, 256>>>(query, key, value, Wq, Wk, Wv,
                          (uint2*)pQp, (uint2*)pKp, pV);

    dim3 gs(SS / 64, BB, HH);      // (32, 2, 12) — h slowest for L2 reuse
    score_bf<<<gs, 256, SC_SMEM>>>((const uint2*)pQp, (const uint2*)pKp,
                                   mask, pb, attn);

    softmax_kernel<<<BB * HH * SS, 128>>>(attn);

    dim3 gp(SS / 64, BB, HH);      // (32, 2, 12)
    pv_kernel<<<gp, 256, PV_SMEM>>>(attn, pV, pC);

    dim3 gg(DD / 128, NT / 128);   // (6, 32)
    gemm_tc<<<gg, 256>>>(pC, Wo, out, bo, NT, DD, DD);
}